// round 6
// baseline (speedup 1.0000x reference)
#include <cuda_runtime.h>
#include <math.h>
#include <stdint.h>

#define B_SZ 4
#define SEQ  2048
#define DIM  1024
#define NH   16
#define HD   64
#define D3   3072
#define M_TOT (B_SZ * SEQ)

// Scratch (device globals — no runtime allocation allowed)
__device__ float g_qkv[(size_t)M_TOT * D3];      // Q,K d-permuted; V plain
__device__ float g_att[(size_t)M_TOT * DIM];     // attention out, d-permuted
__device__ float g_x  [(size_t)M_TOT * DIM];     // x, k-permuted, tf32
__device__ float g_w1 [(size_t)DIM * D3];        // w_qkv^T [3072][1024perm], tf32
__device__ float g_w2 [(size_t)DIM * DIM];       // w_out^T [1024][1024perm], tf32
__device__ float g_vT [(size_t)B_SZ * NH * HD * SEQ];  // V^T [b,h,d,key-perm]

// ---------------------------------------------------------------------------
// Helpers
// ---------------------------------------------------------------------------
__device__ __forceinline__ uint32_t f2tf32(float f) {
    uint32_t r;
    asm("cvt.rna.tf32.f32 %0, %1;" : "=r"(r) : "f"(f));
    return r;
}
__device__ __forceinline__ float tf32f(float f) {
    return __uint_as_float(f2tf32(f));
}
__device__ __forceinline__ void mma_tf32(float c[4], const uint32_t a[4], const uint32_t b[2]) {
    asm volatile(
        "mma.sync.aligned.m16n8k8.row.col.f32.tf32.tf32.f32 "
        "{%0,%1,%2,%3}, {%4,%5,%6,%7}, {%8,%9}, {%0,%1,%2,%3};"
        : "+f"(c[0]), "+f"(c[1]), "+f"(c[2]), "+f"(c[3])
        : "r"(a[0]), "r"(a[1]), "r"(a[2]), "r"(a[3]), "r"(b[0]), "r"(b[1]));
}
__device__ __forceinline__ void cpasync16(void* smem, const void* gmem) {
    uint32_t sa = (uint32_t)__cvta_generic_to_shared(smem);
    asm volatile("cp.async.cg.shared.global [%0], [%1], 16;" :: "r"(sa), "l"(gmem));
}
#define CP_COMMIT() asm volatile("cp.async.commit_group;" ::: "memory")
#define CP_WAIT0()  asm volatile("cp.async.wait_all;" ::: "memory")
#define U(x) __float_as_uint(x)

// ---------------------------------------------------------------------------
// Pre-kernels
// ---------------------------------------------------------------------------
__global__ __launch_bounds__(256) void round_perm(
    const float* __restrict__ in, float* __restrict__ out, int n4, int Kd)
{
    int i = blockIdx.x * blockDim.x + threadIdx.x;
    int stride = gridDim.x * blockDim.x;
    int K4 = Kd / 4;
    for (; i < n4; i += stride) {
        int row = i / K4;
        int col = (i - row * K4) * 4;
        float4 v = ((const float4*)in)[i];
        float* o = out + (size_t)row * Kd + (col & ~31) + ((col & 31) >> 2);
        o[0]  = tf32f(v.x);
        o[8]  = tf32f(v.y);
        o[16] = tf32f(v.z);
        o[24] = tf32f(v.w);
    }
}

// in [K][N] -> out [N][K] with k permuted per 32-block, tf32-rounded.
__global__ __launch_bounds__(256) void transpose_round_perm(
    const float* __restrict__ in, float* __restrict__ out, int K, int N)
{
    __shared__ float t[32][33];
    const int k0 = blockIdx.y * 32, n0 = blockIdx.x * 32;
    const int tx = threadIdx.x, ty = threadIdx.y;
#pragma unroll
    for (int j = 0; j < 4; ++j)
        t[ty + j * 8][tx] = in[(size_t)(k0 + ty + j * 8) * N + n0 + tx];
    __syncthreads();
    const int ptx = (tx & 3) * 8 + (tx >> 2);
#pragma unroll
    for (int j = 0; j < 4; ++j) {
        int row = ty + j * 8;
        out[(size_t)(n0 + row) * K + k0 + ptx] = tf32f(t[tx][row]);
    }
}

// V (plain, in g_qkv cols [2048,3072)) -> vT [b,h,d, key-perm]. Coalesced both sides.
__global__ __launch_bounds__(256) void v_to_vT(
    const float* __restrict__ qkv, float* __restrict__ vT)
{
    __shared__ float t[32][33];
    const int key0 = blockIdx.x * 32;
    const int hh = blockIdx.y >> 1;
    const int d0 = (blockIdx.y & 1) * 32;
    const int b  = blockIdx.z;
    const int tx = threadIdx.x, ty = threadIdx.y;
#pragma unroll
    for (int j = 0; j < 4; ++j)
        t[ty + j * 8][tx] =
            qkv[(size_t)(b * SEQ + key0 + ty + j * 8) * D3 + 2 * DIM + hh * HD + d0 + tx];
    __syncthreads();
    const int pk = (tx & 3) * 8 + (tx >> 2);   // key-perm within 32-block
    float* ob = vT + (((size_t)b * NH + hh) * HD + d0) * SEQ + key0;
#pragma unroll
    for (int j = 0; j < 4; ++j) {
        int d = ty + j * 8;
        ob[(size_t)d * SEQ + pk] = t[tx][d];
    }
}

// ---------------------------------------------------------------------------
// tf32 TC GEMM: C = A@W + bias. A [M][Kperm], Wt [N][Kperm] (both tf32).
// BM=BN=128, BK=32, 256 thr, warp tile 64x32, LDS.128 fragments.
// 2-stage cp.async pipeline, ONE __syncthreads per iteration.
// MODE 0: plain fp32 out. MODE 1: QKV epilogue (Q/K d-perm, V plain), tf32.
// ---------------------------------------------------------------------------
#define TP 36
#define TILE_WORDS (128 * TP)

template<int MODE>
__global__ __launch_bounds__(256, 2) void gemm_tc(
    const float* __restrict__ A, const float* __restrict__ Wt,
    const float* __restrict__ bias, float* __restrict__ C,
    int M, int N, int K)
{
    extern __shared__ float sm[];
    float* AsB = sm;                       // [2][128*36]
    float* BsB = sm + 2 * TILE_WORDS;      // [2][128*36]

    const int tid  = threadIdx.x;
    const int lane = tid & 31;
    const int warp = tid >> 5;
    const int warpM = warp >> 2;
    const int warpN = warp & 3;
    const int g  = lane >> 2;
    const int t4 = lane & 3;
    const int mBase = blockIdx.y * 128;
    const int nBase = blockIdx.x * 128;

    int row_[4], c4_[4];
#pragma unroll
    for (int f = 0; f < 4; ++f) {
        int idx = tid + f * 256;
        row_[f] = idx >> 3;  c4_[f] = (idx & 7) * 4;
    }

    float acc[4][4][4];
#pragma unroll
    for (int mi = 0; mi < 4; ++mi)
#pragma unroll
        for (int ni = 0; ni < 4; ++ni)
#pragma unroll
            for (int r = 0; r < 4; ++r) acc[mi][ni][r] = 0.0f;

    // prologue: tile 0 -> stage 0
    {
        float* As = AsB; float* Bs = BsB;
#pragma unroll
        for (int f = 0; f < 4; ++f) {
            cpasync16(&As[row_[f] * TP + c4_[f]], &A [(size_t)(mBase + row_[f]) * K + c4_[f]]);
            cpasync16(&Bs[row_[f] * TP + c4_[f]], &Wt[(size_t)(nBase + row_[f]) * K + c4_[f]]);
        }
        CP_COMMIT();
    }

    int stage = 0;
    for (int k0 = 0; k0 < K; k0 += 32) {
        CP_WAIT0();
        __syncthreads();             // current stage visible; other stage free

        if (k0 + 32 < K) {
            float* As = AsB + (stage ^ 1) * TILE_WORDS;
            float* Bs = BsB + (stage ^ 1) * TILE_WORDS;
#pragma unroll
            for (int f = 0; f < 4; ++f) {
                cpasync16(&As[row_[f] * TP + c4_[f]],
                          &A [(size_t)(mBase + row_[f]) * K + k0 + 32 + c4_[f]]);
                cpasync16(&Bs[row_[f] * TP + c4_[f]],
                          &Wt[(size_t)(nBase + row_[f]) * K + k0 + 32 + c4_[f]]);
            }
            CP_COMMIT();
        }

        const float* As = AsB + stage * TILE_WORDS;
        const float* Bs = BsB + stage * TILE_WORDS;
#pragma unroll
        for (int jp = 0; jp < 2; ++jp) {
            const int off = t4 * 8 + jp * 4;
            float4 bv[4];
#pragma unroll
            for (int ni = 0; ni < 4; ++ni)
                bv[ni] = *(const float4*)&Bs[(warpN * 32 + ni * 8 + g) * TP + off];
#pragma unroll
            for (int mi = 0; mi < 4; ++mi) {
                float4 av = *(const float4*)&As[(warpM * 64 + mi * 16 + g    ) * TP + off];
                float4 aw = *(const float4*)&As[(warpM * 64 + mi * 16 + g + 8) * TP + off];
                uint32_t a0[4] = {U(av.x), U(aw.x), U(av.y), U(aw.y)};
                uint32_t a1[4] = {U(av.z), U(aw.z), U(av.w), U(aw.w)};
#pragma unroll
                for (int ni = 0; ni < 4; ++ni) {
                    uint32_t b0[2] = {U(bv[ni].x), U(bv[ni].y)};
                    mma_tf32(acc[mi][ni], a0, b0);
                    uint32_t b1[2] = {U(bv[ni].z), U(bv[ni].w)};
                    mma_tf32(acc[mi][ni], a1, b1);
                }
            }
        }
        stage ^= 1;
    }

    // Epilogue
    if (MODE == 0) {
#pragma unroll
        for (int mi = 0; mi < 4; ++mi) {
            int row0 = mBase + warpM * 64 + mi * 16 + g;
#pragma unroll
            for (int ni = 0; ni < 4; ++ni) {
                int c0 = nBase + warpN * 32 + ni * 8 + t4 * 2;
                float2 bv2 = *(const float2*)&bias[c0];
                float2 o0, o1;
                o0.x = acc[mi][ni][0] + bv2.x;
                o0.y = acc[mi][ni][1] + bv2.y;
                o1.x = acc[mi][ni][2] + bv2.x;
                o1.y = acc[mi][ni][3] + bv2.y;
                *(float2*)&C[(size_t)row0 * N + c0]       = o0;
                *(float2*)&C[(size_t)(row0 + 8) * N + c0] = o1;
            }
        }
    } else {
        const int region = nBase >> 10;   // 0=Q, 1=K, 2=V (uniform per CTA)
#pragma unroll
        for (int mi = 0; mi < 4; ++mi) {
            int row0 = mBase + warpM * 64 + mi * 16 + g;
#pragma unroll
            for (int ni = 0; ni < 4; ++ni) {
                int c0 = nBase + warpN * 32 + ni * 8 + t4 * 2;
                float2 bv2 = *(const float2*)&bias[c0];
                float v00 = tf32f(acc[mi][ni][0] + bv2.x);
                float v01 = tf32f(acc[mi][ni][1] + bv2.y);
                float v10 = tf32f(acc[mi][ni][2] + bv2.x);
                float v11 = tf32f(acc[mi][ni][3] + bv2.y);
                if (region < 2) {
                    // Q/K: store d-permuted (feeds attention's k-contraction)
                    int pbase = (c0 & ~31) + 16 * (t4 & 1) + 2 * (ni & 3) + (t4 >> 1);
                    C[(size_t)row0 * N + pbase]           = v00;
                    C[(size_t)row0 * N + pbase + 8]       = v01;
                    C[(size_t)(row0 + 8) * N + pbase]     = v10;
                    C[(size_t)(row0 + 8) * N + pbase + 8] = v11;
                } else {
                    // V: plain coalesced float2 (v_to_vT re-lays it out)
                    float2 o0 = {v00, v01};
                    float2 o1 = {v10, v11};
                    *(float2*)&C[(size_t)row0 * N + c0]       = o0;
                    *(float2*)&C[(size_t)(row0 + 8) * N + c0] = o1;
                }
            }
        }
    }
}

// ---------------------------------------------------------------------------
// Causal flash attention, tf32 TC. Base-2 softmax; Q frags in registers;
// P aliases Q smem; V from vT; one __syncthreads per K/V tile.
// Longest-first qt scheduling.
// ---------------------------------------------------------------------------
#define AQP 68
#define OFF_K (128 * AQP)
#define OFF_V (OFF_K + 2 * 64 * AQP)
#define ATT_SMEM ((OFF_V + 2 * 64 * AQP) * 4)

__global__ __launch_bounds__(256, 2) void attn_fwd_tc(
    const float* __restrict__ qkv, const float* __restrict__ vT,
    float* __restrict__ att)
{
    extern __shared__ float sm[];
    float* QP = sm;   // Q tile, later reused as P tile (warp-private rows)

    const int qt = gridDim.x - 1 - blockIdx.x;   // longest-first
    const int h  = blockIdx.y;
    const int b  = blockIdx.z;
    const int qBase = qt * 128;
    const int tid  = threadIdx.x;
    const int lane = tid & 31;
    const int warp = tid >> 5;
    const int g  = lane >> 2;
    const int t4 = lane & 3;
    const int wrow = warp * 16;
    const float scale = 0.125f * 1.4426950408889634f;   // fold log2(e): base-2 softmax

    const float* kvK = qkv + (size_t)(b * SEQ) * D3 + DIM + h * HD;
    const float* vtb = vT + (((size_t)b * NH + h) * HD) * SEQ;

    // prefetch K/V tile 0
    {
        float* Ks = sm + OFF_K;
        float* Vs = sm + OFF_V;
#pragma unroll
        for (int it = 0; it < 4; ++it) {
            int i = tid + it * 256;
            int r = i >> 4, c4 = (i & 15) * 4;
            cpasync16(&Ks[r * AQP + c4], kvK + (size_t)r * D3 + c4);
            cpasync16(&Vs[r * AQP + c4], vtb + (size_t)r * SEQ + c4);
        }
        CP_COMMIT();
    }

    // Load + scale Q tile (d-permuted in gmem; raw copy preserves perm)
    const float* qb = qkv + (size_t)(b * SEQ + qBase) * D3 + h * HD;
#pragma unroll
    for (int it = 0; it < 8; ++it) {
        int i = tid + it * 256;
        int r = i >> 4, c4 = (i & 15) * 4;
        float4 v = *(const float4*)(qb + (size_t)r * D3 + c4);
        float4 s;
        s.x = v.x * scale; s.y = v.y * scale; s.z = v.z * scale; s.w = v.w * scale;
        *(float4*)&QP[r * AQP + c4] = s;
    }
    __syncthreads();

    // Hoist Q fragments; QP becomes P afterwards.
    float4 qv[4], qw[4];
#pragma unroll
    for (int idx = 0; idx < 4; ++idx) {
        int off = (idx >> 1) * 32 + t4 * 8 + (idx & 1) * 4;
        qv[idx] = *(const float4*)&QP[(wrow + g    ) * AQP + off];
        qw[idx] = *(const float4*)&QP[(wrow + g + 8) * AQP + off];
    }

    float m_i[2] = {-INFINITY, -INFINITY};
    float l_i[2] = {0.0f, 0.0f};
    float O[8][4];
#pragma unroll
    for (int ni = 0; ni < 8; ++ni)
#pragma unroll
        for (int r = 0; r < 4; ++r) O[ni][r] = 0.0f;

    const int nkt = qBase / 64 + 2;
    for (int kt = 0; kt < nkt; ++kt) {
        const int stg = kt & 1;
        CP_WAIT0();
        __syncthreads();             // stage stg visible; stage stg^1 free

        if (kt + 1 < nkt) {
            float* Kn = sm + OFF_K + (stg ^ 1) * 64 * AQP;
            float* Vn = sm + OFF_V + (stg ^ 1) * 64 * AQP;
            const float* srcK = kvK + (size_t)(kt + 1) * 64 * D3;
            const float* srcV = vtb + (kt + 1) * 64;
#pragma unroll
            for (int it = 0; it < 4; ++it) {
                int i = tid + it * 256;
                int r = i >> 4, c4 = (i & 15) * 4;
                cpasync16(&Kn[r * AQP + c4], srcK + (size_t)r * D3 + c4);
                cpasync16(&Vn[r * AQP + c4], srcV + (size_t)r * SEQ + c4);
            }
            CP_COMMIT();
        }

        const float* Ks = sm + OFF_K + stg * 64 * AQP;
        const float* Vs = sm + OFF_V + stg * 64 * AQP;
        const int ktBase = kt * 64;

        // S = Q K^T
        float sc[8][4];
#pragma unroll
        for (int ni = 0; ni < 8; ++ni)
#pragma unroll
            for (int r = 0; r < 4; ++r) sc[ni][r] = 0.0f;

#pragma unroll
        for (int idx = 0; idx < 4; ++idx) {
            const int off = (idx >> 1) * 32 + t4 * 8 + (idx & 1) * 4;
            uint32_t a0[4] = {U(qv[idx].x), U(qw[idx].x), U(qv[idx].y), U(qw[idx].y)};
            uint32_t a1[4] = {U(qv[idx].z), U(qw[idx].z), U(qv[idx].w), U(qw[idx].w)};
#pragma unroll
            for (int ni = 0; ni < 8; ++ni) {
                float4 kv = *(const float4*)&Ks[(ni * 8 + g) * AQP + off];
                uint32_t b0[2] = {U(kv.x), U(kv.y)};
                mma_tf32(sc[ni], a0, b0);
                uint32_t b1[2] = {U(kv.z), U(kv.w)};
                mma_tf32(sc[ni], a1, b1);
            }
        }

        // Causal mask
        if (ktBase + 63 > qBase + wrow) {
            const int r0 = qBase + wrow + g;
            const int r1 = r0 + 8;
#pragma unroll
            for (int ni = 0; ni < 8; ++ni) {
                int c0 = ktBase + ni * 8 + t4 * 2;
                int c1 = c0 + 1;
                if (c0 > r0) sc[ni][0] = -1e30f;
                if (c1 > r0) sc[ni][1] = -1e30f;
                if (c0 > r1) sc[ni][2] = -1e30f;
                if (c1 > r1) sc[ni][3] = -1e30f;
            }
        }

        // Online softmax, base-2
#pragma unroll
        for (int hrow = 0; hrow < 2; ++hrow) {
            const int i0 = hrow * 2, i1 = hrow * 2 + 1;
            float tm = -INFINITY;
#pragma unroll
            for (int ni = 0; ni < 8; ++ni)
                tm = fmaxf(tm, fmaxf(sc[ni][i0], sc[ni][i1]));
            tm = fmaxf(tm, __shfl_xor_sync(0xffffffffu, tm, 1, 4));
            tm = fmaxf(tm, __shfl_xor_sync(0xffffffffu, tm, 2, 4));
            float m_new = fmaxf(m_i[hrow], tm);
            float alpha = exp2f(m_i[hrow] - m_new);
            float rs = 0.0f;
#pragma unroll
            for (int ni = 0; ni < 8; ++ni) {
                sc[ni][i0] = exp2f(sc[ni][i0] - m_new);
                sc[ni][i1] = exp2f(sc[ni][i1] - m_new);
                rs += sc[ni][i0] + sc[ni][i1];
            }
            rs += __shfl_xor_sync(0xffffffffu, rs, 1, 4);
            rs += __shfl_xor_sync(0xffffffffu, rs, 2, 4);
            l_i[hrow] = l_i[hrow] * alpha + rs;
            m_i[hrow] = m_new;
#pragma unroll
            for (int ni = 0; ni < 8; ++ni) {
                O[ni][i0] *= alpha;
                O[ni][i1] *= alpha;
            }
        }

        // P -> smem (key-permuted, tf32), warp-private rows
#pragma unroll
        for (int ni = 0; ni < 8; ++ni) {
            int pbase = (ni & 4) * 8 + 16 * (t4 & 1) + 2 * (ni & 3) + (t4 >> 1);
            QP[(wrow + g    ) * AQP + pbase]     = tf32f(sc[ni][0]);
            QP[(wrow + g    ) * AQP + pbase + 8] = tf32f(sc[ni][1]);
            QP[(wrow + g + 8) * AQP + pbase]     = tf32f(sc[ni][2]);
            QP[(wrow + g + 8) * AQP + pbase + 8] = tf32f(sc[ni][3]);
        }
        __syncwarp();

        // O += P @ V
#pragma unroll
        for (int idx = 0; idx < 4; ++idx) {
            const int off = (idx >> 1) * 32 + t4 * 8 + (idx & 1) * 4;
            float4 pv = *(const float4*)&QP[(wrow + g    ) * AQP + off];
            float4 pw = *(const float4*)&QP[(wrow + g + 8) * AQP + off];
            uint32_t a0[4] = {U(pv.x), U(pw.x), U(pv.y), U(pw.y)};
            uint32_t a1[4] = {U(pv.z), U(pw.z), U(pv.w), U(pw.w)};
#pragma unroll
            for (int ni = 0; ni < 8; ++ni) {
                float4 vv = *(const float4*)&Vs[(ni * 8 + g) * AQP + off];
                uint32_t b0[2] = {U(vv.x), U(vv.y)};
                mma_tf32(O[ni], a0, b0);
                uint32_t b1[2] = {U(vv.z), U(vv.w)};
                mma_tf32(O[ni], a1, b1);
            }
        }
    }

    // Epilogue: normalize, tf32-round, write d-permuted
    float* ob = att + (size_t)(b * SEQ + qBase + wrow) * DIM + h * HD;
    const float inv0 = 1.0f / l_i[0];
    const float inv1 = 1.0f / l_i[1];
#pragma unroll
    for (int ni = 0; ni < 8; ++ni) {
        int pbase = (ni & 4) * 8 + 16 * (t4 & 1) + 2 * (ni & 3) + (t4 >> 1);
        ob[(size_t)g * DIM + pbase]           = tf32f(O[ni][0] * inv0);
        ob[(size_t)g * DIM + pbase + 8]       = tf32f(O[ni][1] * inv0);
        ob[(size_t)(g + 8) * DIM + pbase]     = tf32f(O[ni][2] * inv1);
        ob[(size_t)(g + 8) * DIM + pbase + 8] = tf32f(O[ni][3] * inv1);
    }
}

// ---------------------------------------------------------------------------
extern "C" void kernel_launch(void* const* d_in, const int* in_sizes, int n_in,
                              void* d_out, int out_size)
{
    const float* x     = (const float*)d_in[0];
    const float* w_qkv = (const float*)d_in[1];
    const float* b_qkv = (const float*)d_in[2];
    const float* w_out = (const float*)d_in[3];
    const float* b_out = (const float*)d_in[4];
    float* out = (float*)d_out;

    float *qkv_p, *att_p, *x_p, *w1_p, *w2_p, *vT_p;
    cudaGetSymbolAddress((void**)&qkv_p, g_qkv);
    cudaGetSymbolAddress((void**)&att_p, g_att);
    cudaGetSymbolAddress((void**)&x_p,   g_x);
    cudaGetSymbolAddress((void**)&w1_p,  g_w1);
    cudaGetSymbolAddress((void**)&w2_p,  g_w2);
    cudaGetSymbolAddress((void**)&vT_p,  g_vT);

    // 0) Pre-round + permute/transpose inputs
    round_perm<<<1024, 256>>>(x, x_p, (int)((size_t)M_TOT * DIM / 4), DIM);
    transpose_round_perm<<<dim3(D3 / 32, DIM / 32), dim3(32, 8)>>>(w_qkv, w1_p, DIM, D3);
    transpose_round_perm<<<dim3(DIM / 32, DIM / 32), dim3(32, 8)>>>(w_out, w2_p, DIM, DIM);

    const int gemm_smem = 4 * TILE_WORDS * (int)sizeof(float);  // 73728
    cudaFuncSetAttribute(gemm_tc<1>, cudaFuncAttributeMaxDynamicSharedMemorySize, gemm_smem);
    cudaFuncSetAttribute(gemm_tc<0>, cudaFuncAttributeMaxDynamicSharedMemorySize, gemm_smem);

    // 1) QKV projection
    gemm_tc<1><<<dim3(D3 / 128, M_TOT / 128), 256, gemm_smem>>>(
        x_p, w1_p, b_qkv, qkv_p, M_TOT, D3, DIM);

    // 1b) V -> vT (coalesced transpose + key-perm)
    v_to_vT<<<dim3(SEQ / 32, NH * 2, B_SZ), dim3(32, 8)>>>(qkv_p, vT_p);

    // 2) Causal flash attention
    cudaFuncSetAttribute(attn_fwd_tc, cudaFuncAttributeMaxDynamicSharedMemorySize, ATT_SMEM);
    attn_fwd_tc<<<dim3(SEQ / 128, NH, B_SZ), 256, ATT_SMEM>>>(qkv_p, vT_p, att_p);

    // 3) Output projection
    gemm_tc<0><<<dim3(DIM / 128, M_TOT / 128), 256, gemm_smem>>>(
        att_p, w2_p, b_out, out, M_TOT, DIM, DIM);
}

// round 7
// speedup vs baseline: 1.1340x; 1.1340x over previous
#include <cuda_runtime.h>
#include <math.h>
#include <stdint.h>

#define B_SZ 4
#define SEQ  2048
#define DIM  1024
#define NH   16
#define HD   64
#define D3   3072
#define M_TOT (B_SZ * SEQ)

// Scratch (device globals — no runtime allocation allowed)
__device__ float g_qkv[(size_t)M_TOT * D3];   // tf32-rounded qkv (plain layout)
__device__ float g_att[(size_t)M_TOT * DIM];  // tf32-rounded attention out
__device__ float g_x  [(size_t)M_TOT * DIM];  // tf32-rounded x
__device__ float g_w1 [(size_t)DIM * D3];     // tf32-rounded w_qkv [K][N]
__device__ float g_w2 [(size_t)DIM * DIM];    // tf32-rounded w_out [K][N]

// ---------------------------------------------------------------------------
// Helpers
// ---------------------------------------------------------------------------
__device__ __forceinline__ uint32_t f2tf32(float f) {
    uint32_t r;
    asm("cvt.rna.tf32.f32 %0, %1;" : "=r"(r) : "f"(f));
    return r;
}
__device__ __forceinline__ float tf32f(float f) {
    return __uint_as_float(f2tf32(f));
}
__device__ __forceinline__ void mma_tf32(float c[4], const uint32_t a[4], const uint32_t b[2]) {
    asm volatile(
        "mma.sync.aligned.m16n8k8.row.col.f32.tf32.tf32.f32 "
        "{%0,%1,%2,%3}, {%4,%5,%6,%7}, {%8,%9}, {%0,%1,%2,%3};"
        : "+f"(c[0]), "+f"(c[1]), "+f"(c[2]), "+f"(c[3])
        : "r"(a[0]), "r"(a[1]), "r"(a[2]), "r"(a[3]), "r"(b[0]), "r"(b[1]));
}
__device__ __forceinline__ void cpasync16(void* smem, const void* gmem) {
    uint32_t sa = (uint32_t)__cvta_generic_to_shared(smem);
    asm volatile("cp.async.cg.shared.global [%0], [%1], 16;" :: "r"(sa), "l"(gmem));
}
#define CP_COMMIT() asm volatile("cp.async.commit_group;" ::: "memory")
#define CP_WAIT0()  asm volatile("cp.async.wait_all;" ::: "memory")

// ---------------------------------------------------------------------------
// Pre-round a float array to tf32 bits (vectorized).
// ---------------------------------------------------------------------------
__global__ __launch_bounds__(256) void round_tf32(
    const float* __restrict__ in, float* __restrict__ out, int n4)
{
    int i = blockIdx.x * blockDim.x + threadIdx.x;
    int stride = gridDim.x * blockDim.x;
    for (; i < n4; i += stride) {
        float4 v = ((const float4*)in)[i];
        float4 o;
        o.x = tf32f(v.x); o.y = tf32f(v.y); o.z = tf32f(v.z); o.w = tf32f(v.w);
        ((float4*)out)[i] = o;
    }
}

// ---------------------------------------------------------------------------
// tf32 TC GEMM with bias: C = A@W + bias (inputs pre-rounded to tf32).
// BM=BN=128, BK=32, 256 thr, 8 warps (2x4), warp tile 64x32.
// R4-proven layouts: As [m][k] pitch 36, Bs [k][n] pitch 136, scalar frag LDS
// (conflict-free). 2-stage cp.async pipeline with ONE __syncthreads per iter.
// ROUND_OUT=1: round outputs to tf32 (intermediates feeding later tf32 mma).
// ---------------------------------------------------------------------------
#define AsP 36
#define BsP 136
#define STG_A (128 * AsP)
#define STG_B (32 * BsP)

template<int ROUND_OUT>
__global__ __launch_bounds__(256, 2) void gemm_bias_tc(
    const float* __restrict__ A, const float* __restrict__ W,
    const float* __restrict__ bias, float* __restrict__ C,
    int M, int N, int K)
{
    extern __shared__ float sm[];
    float* AsB = sm;                 // [2][128*36]
    float* BsB = sm + 2 * STG_A;     // [2][32*136]

    const int tid  = threadIdx.x;
    const int lane = tid & 31;
    const int warp = tid >> 5;
    const int warpM = warp >> 2;
    const int warpN = warp & 3;
    const int g  = lane >> 2;
    const int t4 = lane & 3;
    const int mBase = blockIdx.y * 128;
    const int nBase = blockIdx.x * 128;

    int aRow[4], aC4[4], bRow[4], bC4[4];
#pragma unroll
    for (int f = 0; f < 4; ++f) {
        int idx = tid + f * 256;
        aRow[f] = idx >> 3;  aC4[f] = (idx & 7) * 4;     // A: 128 rows x 8 chunks
        bRow[f] = idx >> 5;  bC4[f] = (idx & 31) * 4;    // B: 32 rows x 32 chunks
    }

    float acc[4][4][4];
#pragma unroll
    for (int mi = 0; mi < 4; ++mi)
#pragma unroll
        for (int ni = 0; ni < 4; ++ni)
#pragma unroll
            for (int r = 0; r < 4; ++r) acc[mi][ni][r] = 0.0f;

    // prologue: tile 0 -> stage 0
    {
        float* As = AsB; float* Bs = BsB;
#pragma unroll
        for (int f = 0; f < 4; ++f) {
            cpasync16(&As[aRow[f] * AsP + aC4[f]], &A[(size_t)(mBase + aRow[f]) * K + aC4[f]]);
            cpasync16(&Bs[bRow[f] * BsP + bC4[f]], &W[(size_t)bRow[f] * N + nBase + bC4[f]]);
        }
        CP_COMMIT();
    }

    int stage = 0;
    for (int k0 = 0; k0 < K; k0 += 32) {
        CP_WAIT0();
        __syncthreads();      // current stage data visible; other stage consumed

        if (k0 + 32 < K) {
            float* As = AsB + (stage ^ 1) * STG_A;
            float* Bs = BsB + (stage ^ 1) * STG_B;
#pragma unroll
            for (int f = 0; f < 4; ++f) {
                cpasync16(&As[aRow[f] * AsP + aC4[f]],
                          &A[(size_t)(mBase + aRow[f]) * K + k0 + 32 + aC4[f]]);
                cpasync16(&Bs[bRow[f] * BsP + bC4[f]],
                          &W[(size_t)(k0 + 32 + bRow[f]) * N + nBase + bC4[f]]);
            }
            CP_COMMIT();
        }

        const float* As = AsB + stage * STG_A;
        const float* Bs = BsB + stage * STG_B;
#pragma unroll
        for (int kb = 0; kb < 32; kb += 8) {
            uint32_t afr[4][4], bfr[4][2];
#pragma unroll
            for (int mi = 0; mi < 4; ++mi) {
                int m = warpM * 64 + mi * 16;
                afr[mi][0] = __float_as_uint(As[(m + g    ) * AsP + kb + t4    ]);
                afr[mi][1] = __float_as_uint(As[(m + g + 8) * AsP + kb + t4    ]);
                afr[mi][2] = __float_as_uint(As[(m + g    ) * AsP + kb + t4 + 4]);
                afr[mi][3] = __float_as_uint(As[(m + g + 8) * AsP + kb + t4 + 4]);
            }
#pragma unroll
            for (int ni = 0; ni < 4; ++ni) {
                int n = warpN * 32 + ni * 8;
                bfr[ni][0] = __float_as_uint(Bs[(kb + t4    ) * BsP + n + g]);
                bfr[ni][1] = __float_as_uint(Bs[(kb + t4 + 4) * BsP + n + g]);
            }
#pragma unroll
            for (int mi = 0; mi < 4; ++mi)
#pragma unroll
                for (int ni = 0; ni < 4; ++ni)
                    mma_tf32(acc[mi][ni], afr[mi], bfr[ni]);
        }
        stage ^= 1;
    }

    // Epilogue: bias + float2 stores (optionally tf32-rounded)
#pragma unroll
    for (int mi = 0; mi < 4; ++mi) {
        int row0 = mBase + warpM * 64 + mi * 16 + g;
#pragma unroll
        for (int ni = 0; ni < 4; ++ni) {
            int col = nBase + warpN * 32 + ni * 8 + t4 * 2;
            float2 bv = *(const float2*)&bias[col];
            float2 o0, o1;
            if (ROUND_OUT) {
                o0.x = tf32f(acc[mi][ni][0] + bv.x);
                o0.y = tf32f(acc[mi][ni][1] + bv.y);
                o1.x = tf32f(acc[mi][ni][2] + bv.x);
                o1.y = tf32f(acc[mi][ni][3] + bv.y);
            } else {
                o0.x = acc[mi][ni][0] + bv.x;
                o0.y = acc[mi][ni][1] + bv.y;
                o1.x = acc[mi][ni][2] + bv.x;
                o1.y = acc[mi][ni][3] + bv.y;
            }
            *(float2*)&C[(size_t)row0 * N + col]       = o0;
            *(float2*)&C[(size_t)(row0 + 8) * N + col] = o1;
        }
    }
}

// ---------------------------------------------------------------------------
// Causal flash attention, tf32 TC (R4 layouts) with:
//  - Q fragments hoisted to registers (loaded once)
//  - P aliases the Q smem buffer -> 104KB smem -> 2 CTAs/SM
//  - single __syncthreads per K/V tile, base-2 softmax
//  - longest-first qt scheduling
// ---------------------------------------------------------------------------
#define AQP 68   // Q/P/K pitch: scalar frag reads -> bank 4g+t4 (conflict-free)
#define AVP 72   // V pitch:      scalar frag reads -> bank 8t4+g (conflict-free)
#define OFF_K (128 * AQP)
#define OFF_V (OFF_K + 2 * 64 * AQP)
#define ATT_SMEM ((OFF_V + 2 * 64 * AVP) * 4)   // 106496 B

__global__ __launch_bounds__(256, 2) void attn_fwd_tc(
    const float* __restrict__ qkv, float* __restrict__ att)
{
    extern __shared__ float sm[];
    float* QP = sm;   // Q tile; later reused as P tile (warp-private rows)

    const int qt = gridDim.x - 1 - blockIdx.x;   // longest-first
    const int h  = blockIdx.y;
    const int b  = blockIdx.z;
    const int qBase = qt * 128;
    const int tid  = threadIdx.x;
    const int lane = tid & 31;
    const int warp = tid >> 5;
    const int g  = lane >> 2;
    const int t4 = lane & 3;
    const int wrow = warp * 16;
    const float scale = 0.125f * 1.4426950408889634f;  // fold log2(e)

    const float* kvK = qkv + (size_t)(b * SEQ) * D3 + DIM + h * HD;   // K base

    // prefetch K/V tile 0
    {
        float* Ks = sm + OFF_K;
        float* Vs = sm + OFF_V;
#pragma unroll
        for (int it = 0; it < 4; ++it) {
            int i = tid + it * 256;
            int r = i >> 4, c4 = (i & 15) * 4;
            cpasync16(&Ks[r * AQP + c4], kvK + (size_t)r * D3 + c4);
            cpasync16(&Vs[r * AVP + c4], kvK + DIM + (size_t)r * D3 + c4);
        }
        CP_COMMIT();
    }

    // Load + scale Q tile into smem (128x64)
    const float* qb = qkv + (size_t)(b * SEQ + qBase) * D3 + h * HD;
#pragma unroll
    for (int it = 0; it < 8; ++it) {
        int i = tid + it * 256;
        int r = i >> 4, c4 = (i & 15) * 4;
        float4 v = *(const float4*)(qb + (size_t)r * D3 + c4);
        float4 s;
        s.x = v.x * scale; s.y = v.y * scale; s.z = v.z * scale; s.w = v.w * scale;
        *(float4*)&QP[r * AQP + c4] = s;
    }
    __syncthreads();

    // Hoist Q fragments to registers (scalar conflict-free pattern, once).
    // After this, QP rows [wrow, wrow+16) are warp-private -> reused for P.
    uint32_t qf[8][4];
#pragma unroll
    for (int kk = 0; kk < 8; ++kk) {
        int kb8 = kk * 8;
        qf[kk][0] = __float_as_uint(QP[(wrow + g    ) * AQP + kb8 + t4    ]);
        qf[kk][1] = __float_as_uint(QP[(wrow + g + 8) * AQP + kb8 + t4    ]);
        qf[kk][2] = __float_as_uint(QP[(wrow + g    ) * AQP + kb8 + t4 + 4]);
        qf[kk][3] = __float_as_uint(QP[(wrow + g + 8) * AQP + kb8 + t4 + 4]);
    }

    float m_i[2] = {-INFINITY, -INFINITY};
    float l_i[2] = {0.0f, 0.0f};
    float O[8][4];
#pragma unroll
    for (int ni = 0; ni < 8; ++ni)
#pragma unroll
        for (int r = 0; r < 4; ++r) O[ni][r] = 0.0f;

    const int nkt = qBase / 64 + 2;
    for (int kt = 0; kt < nkt; ++kt) {
        const int stg = kt & 1;
        CP_WAIT0();
        __syncthreads();   // tile kt arrived; all warps done with other stage

        if (kt + 1 < nkt) {
            float* Kn = sm + OFF_K + (stg ^ 1) * 64 * AQP;
            float* Vn = sm + OFF_V + (stg ^ 1) * 64 * AVP;
            const float* src = kvK + (size_t)(kt + 1) * 64 * D3;
#pragma unroll
            for (int it = 0; it < 4; ++it) {
                int i = tid + it * 256;
                int r = i >> 4, c4 = (i & 15) * 4;
                cpasync16(&Kn[r * AQP + c4], src + (size_t)r * D3 + c4);
                cpasync16(&Vn[r * AVP + c4], src + DIM + (size_t)r * D3 + c4);
            }
            CP_COMMIT();
        }

        const float* Ks = sm + OFF_K + stg * 64 * AQP;
        const float* Vs = sm + OFF_V + stg * 64 * AVP;
        const int ktBase = kt * 64;

        // S[16x64] per warp = Q_warp . K^T
        float sc[8][4];
#pragma unroll
        for (int ni = 0; ni < 8; ++ni)
#pragma unroll
            for (int r = 0; r < 4; ++r) sc[ni][r] = 0.0f;

#pragma unroll
        for (int kk = 0; kk < 8; ++kk) {
            int kb8 = kk * 8;
#pragma unroll
            for (int ni = 0; ni < 8; ++ni) {
                uint32_t bb[2];
                bb[0] = __float_as_uint(Ks[(ni * 8 + g) * AQP + kb8 + t4    ]);
                bb[1] = __float_as_uint(Ks[(ni * 8 + g) * AQP + kb8 + t4 + 4]);
                mma_tf32(sc[ni], qf[kk], bb);
            }
        }

        // Causal mask
        if (ktBase + 63 > qBase + wrow) {
            const int r0 = qBase + wrow + g;
            const int r1 = r0 + 8;
#pragma unroll
            for (int ni = 0; ni < 8; ++ni) {
                int c0 = ktBase + ni * 8 + t4 * 2;
                int c1 = c0 + 1;
                if (c0 > r0) sc[ni][0] = -1e30f;
                if (c1 > r0) sc[ni][1] = -1e30f;
                if (c0 > r1) sc[ni][2] = -1e30f;
                if (c1 > r1) sc[ni][3] = -1e30f;
            }
        }

        // Online softmax, base-2, quad-reduce
#pragma unroll
        for (int hrow = 0; hrow < 2; ++hrow) {
            const int i0 = hrow * 2, i1 = hrow * 2 + 1;
            float tm = -INFINITY;
#pragma unroll
            for (int ni = 0; ni < 8; ++ni)
                tm = fmaxf(tm, fmaxf(sc[ni][i0], sc[ni][i1]));
            tm = fmaxf(tm, __shfl_xor_sync(0xffffffffu, tm, 1, 4));
            tm = fmaxf(tm, __shfl_xor_sync(0xffffffffu, tm, 2, 4));
            float m_new = fmaxf(m_i[hrow], tm);
            float alpha = exp2f(m_i[hrow] - m_new);
            float rs = 0.0f;
#pragma unroll
            for (int ni = 0; ni < 8; ++ni) {
                sc[ni][i0] = exp2f(sc[ni][i0] - m_new);
                sc[ni][i1] = exp2f(sc[ni][i1] - m_new);
                rs += sc[ni][i0] + sc[ni][i1];
            }
            rs += __shfl_xor_sync(0xffffffffu, rs, 1, 4);
            rs += __shfl_xor_sync(0xffffffffu, rs, 2, 4);
            l_i[hrow] = l_i[hrow] * alpha + rs;
            m_i[hrow] = m_new;
#pragma unroll
            for (int ni = 0; ni < 8; ++ni) {
                O[ni][i0] *= alpha;
                O[ni][i1] *= alpha;
            }
        }

        // P -> QP smem (tf32), warp-private rows
#pragma unroll
        for (int ni = 0; ni < 8; ++ni) {
            QP[(wrow + g    ) * AQP + ni * 8 + t4 * 2    ] = tf32f(sc[ni][0]);
            QP[(wrow + g    ) * AQP + ni * 8 + t4 * 2 + 1] = tf32f(sc[ni][1]);
            QP[(wrow + g + 8) * AQP + ni * 8 + t4 * 2    ] = tf32f(sc[ni][2]);
            QP[(wrow + g + 8) * AQP + ni * 8 + t4 * 2 + 1] = tf32f(sc[ni][3]);
        }
        __syncwarp();

        // O += P @ V
#pragma unroll
        for (int kk = 0; kk < 8; ++kk) {
            int kb8 = kk * 8;
            uint32_t a[4];
            a[0] = __float_as_uint(QP[(wrow + g    ) * AQP + kb8 + t4    ]);
            a[1] = __float_as_uint(QP[(wrow + g + 8) * AQP + kb8 + t4    ]);
            a[2] = __float_as_uint(QP[(wrow + g    ) * AQP + kb8 + t4 + 4]);
            a[3] = __float_as_uint(QP[(wrow + g + 8) * AQP + kb8 + t4 + 4]);
#pragma unroll
            for (int ni = 0; ni < 8; ++ni) {
                uint32_t bb[2];
                bb[0] = __float_as_uint(Vs[(kb8 + t4    ) * AVP + ni * 8 + g]);
                bb[1] = __float_as_uint(Vs[(kb8 + t4 + 4) * AVP + ni * 8 + g]);
                mma_tf32(O[ni], a, bb);
            }
        }
    }

    // Epilogue: normalize, tf32-round (feeds tf32 out-GEMM), plain layout
    float* ob = att + (size_t)(b * SEQ + qBase + wrow) * DIM + h * HD;
    const float inv0 = 1.0f / l_i[0];
    const float inv1 = 1.0f / l_i[1];
#pragma unroll
    for (int ni = 0; ni < 8; ++ni) {
        int col = ni * 8 + t4 * 2;
        float2 o0, o1;
        o0.x = tf32f(O[ni][0] * inv0); o0.y = tf32f(O[ni][1] * inv0);
        o1.x = tf32f(O[ni][2] * inv1); o1.y = tf32f(O[ni][3] * inv1);
        *(float2*)(ob + (size_t)(g    ) * DIM + col) = o0;
        *(float2*)(ob + (size_t)(g + 8) * DIM + col) = o1;
    }
}

// ---------------------------------------------------------------------------
extern "C" void kernel_launch(void* const* d_in, const int* in_sizes, int n_in,
                              void* d_out, int out_size)
{
    const float* x     = (const float*)d_in[0];
    const float* w_qkv = (const float*)d_in[1];
    const float* b_qkv = (const float*)d_in[2];
    const float* w_out = (const float*)d_in[3];
    const float* b_out = (const float*)d_in[4];
    float* out = (float*)d_out;

    float *qkv_p, *att_p, *x_p, *w1_p, *w2_p;
    cudaGetSymbolAddress((void**)&qkv_p, g_qkv);
    cudaGetSymbolAddress((void**)&att_p, g_att);
    cudaGetSymbolAddress((void**)&x_p,   g_x);
    cudaGetSymbolAddress((void**)&w1_p,  g_w1);
    cudaGetSymbolAddress((void**)&w2_p,  g_w2);

    // 0) Pre-round inputs to tf32
    round_tf32<<<512, 256>>>(x,     x_p,  (int)((size_t)M_TOT * DIM / 4));
    round_tf32<<<256, 256>>>(w_qkv, w1_p, (int)((size_t)DIM * D3 / 4));
    round_tf32<<<128, 256>>>(w_out, w2_p, (int)((size_t)DIM * DIM / 4));

    const int gemm_smem = (2 * STG_A + 2 * STG_B) * (int)sizeof(float);
    cudaFuncSetAttribute(gemm_bias_tc<1>, cudaFuncAttributeMaxDynamicSharedMemorySize, gemm_smem);
    cudaFuncSetAttribute(gemm_bias_tc<0>, cudaFuncAttributeMaxDynamicSharedMemorySize, gemm_smem);

    // 1) QKV projection (rounds output to tf32)
    gemm_bias_tc<1><<<dim3(D3 / 128, M_TOT / 128), 256, gemm_smem>>>(
        x_p, w1_p, b_qkv, qkv_p, M_TOT, D3, DIM);

    // 2) Causal flash attention
    cudaFuncSetAttribute(attn_fwd_tc, cudaFuncAttributeMaxDynamicSharedMemorySize, ATT_SMEM);
    attn_fwd_tc<<<dim3(SEQ / 128, NH, B_SZ), 256, ATT_SMEM>>>(qkv_p, att_p);

    // 3) Output projection (full fp32 output)
    gemm_bias_tc<0><<<dim3(DIM / 128, M_TOT / 128), 256, gemm_smem>>>(
        att_p, w2_p, b_out, out, M_TOT, DIM, DIM);
}

// round 8
// speedup vs baseline: 1.1405x; 1.0058x over previous
#include <cuda_runtime.h>
#include <math.h>
#include <stdint.h>

#define B_SZ 4
#define SEQ  2048
#define DIM  1024
#define NH   16
#define HD   64
#define D3   3072
#define M_TOT (B_SZ * SEQ)

// Scratch (device globals — no runtime allocation allowed)
__device__ float g_qkv[(size_t)M_TOT * D3];   // tf32-rounded qkv (plain layout)
__device__ float g_att[(size_t)M_TOT * DIM];  // attention out, d-PERMUTED, tf32
__device__ float g_x  [(size_t)M_TOT * DIM];  // x, k-PERMUTED, tf32
__device__ float g_w1 [(size_t)DIM * D3];     // w_qkv^T [3072][1024 kperm], tf32
__device__ float g_w2 [(size_t)DIM * DIM];    // w_out^T [1024][1024 kperm], tf32

// ---------------------------------------------------------------------------
// Helpers
// ---------------------------------------------------------------------------
__device__ __forceinline__ uint32_t f2tf32(float f) {
    uint32_t r;
    asm("cvt.rna.tf32.f32 %0, %1;" : "=r"(r) : "f"(f));
    return r;
}
__device__ __forceinline__ float tf32f(float f) {
    return __uint_as_float(f2tf32(f));
}
__device__ __forceinline__ void mma_tf32(float c[4], const uint32_t a[4], const uint32_t b[2]) {
    asm volatile(
        "mma.sync.aligned.m16n8k8.row.col.f32.tf32.tf32.f32 "
        "{%0,%1,%2,%3}, {%4,%5,%6,%7}, {%8,%9}, {%0,%1,%2,%3};"
        : "+f"(c[0]), "+f"(c[1]), "+f"(c[2]), "+f"(c[3])
        : "r"(a[0]), "r"(a[1]), "r"(a[2]), "r"(a[3]), "r"(b[0]), "r"(b[1]));
}
__device__ __forceinline__ void cpasync16(void* smem, const void* gmem) {
    uint32_t sa = (uint32_t)__cvta_generic_to_shared(smem);
    asm volatile("cp.async.cg.shared.global [%0], [%1], 16;" :: "r"(sa), "l"(gmem));
}
#define CP_COMMIT() asm volatile("cp.async.commit_group;" ::: "memory")
#define CP_WAIT0()  asm volatile("cp.async.wait_all;" ::: "memory")
#define U(x) __float_as_uint(x)

// ---------------------------------------------------------------------------
// Pre-kernels: tf32-round with k-permutation p(k) = (k%4)*8 + k/4 per 32-block
// ---------------------------------------------------------------------------
__global__ __launch_bounds__(256) void round_perm(
    const float* __restrict__ in, float* __restrict__ out, int n4, int Kd)
{
    int i = blockIdx.x * blockDim.x + threadIdx.x;
    int stride = gridDim.x * blockDim.x;
    int K4 = Kd / 4;
    for (; i < n4; i += stride) {
        int row = i / K4;
        int col = (i - row * K4) * 4;
        float4 v = ((const float4*)in)[i];
        float* o = out + (size_t)row * Kd + (col & ~31) + ((col & 31) >> 2);
        o[0]  = tf32f(v.x);
        o[8]  = tf32f(v.y);
        o[16] = tf32f(v.z);
        o[24] = tf32f(v.w);
    }
}

// in [K][N] -> out [N][K] with k permuted per 32-block, tf32-rounded.
__global__ __launch_bounds__(256) void transpose_round_perm(
    const float* __restrict__ in, float* __restrict__ out, int K, int N)
{
    __shared__ float t[32][33];
    const int k0 = blockIdx.y * 32, n0 = blockIdx.x * 32;
    const int tx = threadIdx.x, ty = threadIdx.y;
#pragma unroll
    for (int j = 0; j < 4; ++j)
        t[ty + j * 8][tx] = in[(size_t)(k0 + ty + j * 8) * N + n0 + tx];
    __syncthreads();
    const int ptx = (tx & 3) * 8 + (tx >> 2);
#pragma unroll
    for (int j = 0; j < 4; ++j) {
        int row = ty + j * 8;
        out[(size_t)(n0 + row) * K + k0 + ptx] = tf32f(t[tx][row]);
    }
}

// ---------------------------------------------------------------------------
// tf32 TC GEMM: C = A@W + bias.
// A [M][Kperm], Wt [N][Kperm] (both tf32, k-permuted per 32-block).
// BM=BN=128, BK=32, 128 threads (4 warps, 2x2), warp tile 64x64.
// SMEM: pitch 32 words, 16B chunks XOR-swizzled: chunk' = chunk ^ (row&7).
// All fragment loads are conflict-free LDS.128.
// ROUND_OUT=1: tf32-round outputs (intermediates feeding later tf32 mma).
// ---------------------------------------------------------------------------
#define GSTG (128 * 32)   // words per tile stage (16KB)

template<int ROUND_OUT>
__global__ __launch_bounds__(128, 2) void gemm_tc(
    const float* __restrict__ A, const float* __restrict__ Wt,
    const float* __restrict__ bias, float* __restrict__ C,
    int M, int N, int K)
{
    extern __shared__ float sm[];
    float* AsB = sm;               // [2][128*32]
    float* BsB = sm + 2 * GSTG;    // [2][128*32]

    const int tid  = threadIdx.x;
    const int lane = tid & 31;
    const int warp = tid >> 5;
    const int warpM = warp >> 1;       // 0..1 -> 64 rows
    const int warpN = warp & 1;        // 0..1 -> 64 cols
    const int g  = lane >> 2;          // 0..7
    const int t4 = lane & 3;           // 0..3
    const int mBase = blockIdx.y * 128;
    const int nBase = blockIdx.x * 128;

    // cp.async coordinates: 1024 chunks per tile, 8 per thread
    int row_[8], sw4_[8], gc4_[8];
#pragma unroll
    for (int f = 0; f < 8; ++f) {
        int idx = tid + f * 128;
        int r = idx >> 3, c = idx & 7;
        row_[f] = r;
        gc4_[f] = c * 4;                    // global word offset of chunk
        sw4_[f] = (c ^ (r & 7)) * 4;        // swizzled smem word offset
    }

    float acc[4][8][4];
#pragma unroll
    for (int mi = 0; mi < 4; ++mi)
#pragma unroll
        for (int ni = 0; ni < 8; ++ni)
#pragma unroll
            for (int r = 0; r < 4; ++r) acc[mi][ni][r] = 0.0f;

    // prologue: tile 0 -> stage 0
    {
        float* As = AsB; float* Bs = BsB;
#pragma unroll
        for (int f = 0; f < 8; ++f) {
            cpasync16(&As[row_[f] * 32 + sw4_[f]],
                      &A [(size_t)(mBase + row_[f]) * K + gc4_[f]]);
            cpasync16(&Bs[row_[f] * 32 + sw4_[f]],
                      &Wt[(size_t)(nBase + row_[f]) * K + gc4_[f]]);
        }
        CP_COMMIT();
    }

    int stage = 0;
    for (int k0 = 0; k0 < K; k0 += 32) {
        CP_WAIT0();
        __syncthreads();

        if (k0 + 32 < K) {
            float* As = AsB + (stage ^ 1) * GSTG;
            float* Bs = BsB + (stage ^ 1) * GSTG;
#pragma unroll
            for (int f = 0; f < 8; ++f) {
                cpasync16(&As[row_[f] * 32 + sw4_[f]],
                          &A [(size_t)(mBase + row_[f]) * K + k0 + 32 + gc4_[f]]);
                cpasync16(&Bs[row_[f] * 32 + sw4_[f]],
                          &Wt[(size_t)(nBase + row_[f]) * K + k0 + 32 + gc4_[f]]);
            }
            CP_COMMIT();
        }

        const float* As = AsB + stage * GSTG;
        const float* Bs = BsB + stage * GSTG;

#pragma unroll
        for (int jp = 0; jp < 2; ++jp) {
            const int swoff = ((2 * t4 + jp) ^ g) * 4;   // swizzled chunk for this thread
            float4 bv[8];
#pragma unroll
            for (int ni = 0; ni < 8; ++ni)
                bv[ni] = *(const float4*)&Bs[(warpN * 64 + ni * 8 + g) * 32 + swoff];
#pragma unroll
            for (int mi = 0; mi < 4; ++mi) {
                float4 av = *(const float4*)&As[(warpM * 64 + mi * 16 + g    ) * 32 + swoff];
                float4 aw = *(const float4*)&As[(warpM * 64 + mi * 16 + g + 8) * 32 + swoff];
                uint32_t a_lo[4] = {U(av.x), U(aw.x), U(av.y), U(aw.y)};
                uint32_t a_hi[4] = {U(av.z), U(aw.z), U(av.w), U(aw.w)};
#pragma unroll
                for (int ni = 0; ni < 8; ++ni) {
                    uint32_t b_lo[2] = {U(bv[ni].x), U(bv[ni].y)};
                    mma_tf32(acc[mi][ni], a_lo, b_lo);
                    uint32_t b_hi[2] = {U(bv[ni].z), U(bv[ni].w)};
                    mma_tf32(acc[mi][ni], a_hi, b_hi);
                }
            }
        }
        stage ^= 1;
    }

    // Epilogue: bias + float2 stores (optionally tf32-rounded)
#pragma unroll
    for (int mi = 0; mi < 4; ++mi) {
        int row0 = mBase + warpM * 64 + mi * 16 + g;
#pragma unroll
        for (int ni = 0; ni < 8; ++ni) {
            int col = nBase + warpN * 64 + ni * 8 + t4 * 2;
            float2 bv = *(const float2*)&bias[col];
            float2 o0, o1;
            if (ROUND_OUT) {
                o0.x = tf32f(acc[mi][ni][0] + bv.x);
                o0.y = tf32f(acc[mi][ni][1] + bv.y);
                o1.x = tf32f(acc[mi][ni][2] + bv.x);
                o1.y = tf32f(acc[mi][ni][3] + bv.y);
            } else {
                o0.x = acc[mi][ni][0] + bv.x;
                o0.y = acc[mi][ni][1] + bv.y;
                o1.x = acc[mi][ni][2] + bv.x;
                o1.y = acc[mi][ni][3] + bv.y;
            }
            *(float2*)&C[(size_t)row0 * N + col]       = o0;
            *(float2*)&C[(size_t)(row0 + 8) * N + col] = o1;
        }
    }
}

// ---------------------------------------------------------------------------
// Causal flash attention, tf32 TC (R7 mainloop, unchanged / measured-good).
// Only the epilogue differs: writes att d-PERMUTED to feed the out-GEMM.
// ---------------------------------------------------------------------------
#define AQP 68
#define AVP 72
#define OFF_K (128 * AQP)
#define OFF_V (OFF_K + 2 * 64 * AQP)
#define ATT_SMEM ((OFF_V + 2 * 64 * AVP) * 4)

__global__ __launch_bounds__(256, 2) void attn_fwd_tc(
    const float* __restrict__ qkv, float* __restrict__ att)
{
    extern __shared__ float sm[];
    float* QP = sm;

    const int qt = gridDim.x - 1 - blockIdx.x;   // longest-first
    const int h  = blockIdx.y;
    const int b  = blockIdx.z;
    const int qBase = qt * 128;
    const int tid  = threadIdx.x;
    const int lane = tid & 31;
    const int warp = tid >> 5;
    const int g  = lane >> 2;
    const int t4 = lane & 3;
    const int wrow = warp * 16;
    const float scale = 0.125f * 1.4426950408889634f;

    const float* kvK = qkv + (size_t)(b * SEQ) * D3 + DIM + h * HD;

    {
        float* Ks = sm + OFF_K;
        float* Vs = sm + OFF_V;
#pragma unroll
        for (int it = 0; it < 4; ++it) {
            int i = tid + it * 256;
            int r = i >> 4, c4 = (i & 15) * 4;
            cpasync16(&Ks[r * AQP + c4], kvK + (size_t)r * D3 + c4);
            cpasync16(&Vs[r * AVP + c4], kvK + DIM + (size_t)r * D3 + c4);
        }
        CP_COMMIT();
    }

    const float* qb = qkv + (size_t)(b * SEQ + qBase) * D3 + h * HD;
#pragma unroll
    for (int it = 0; it < 8; ++it) {
        int i = tid + it * 256;
        int r = i >> 4, c4 = (i & 15) * 4;
        float4 v = *(const float4*)(qb + (size_t)r * D3 + c4);
        float4 s;
        s.x = v.x * scale; s.y = v.y * scale; s.z = v.z * scale; s.w = v.w * scale;
        *(float4*)&QP[r * AQP + c4] = s;
    }
    __syncthreads();

    uint32_t qf[8][4];
#pragma unroll
    for (int kk = 0; kk < 8; ++kk) {
        int kb8 = kk * 8;
        qf[kk][0] = __float_as_uint(QP[(wrow + g    ) * AQP + kb8 + t4    ]);
        qf[kk][1] = __float_as_uint(QP[(wrow + g + 8) * AQP + kb8 + t4    ]);
        qf[kk][2] = __float_as_uint(QP[(wrow + g    ) * AQP + kb8 + t4 + 4]);
        qf[kk][3] = __float_as_uint(QP[(wrow + g + 8) * AQP + kb8 + t4 + 4]);
    }

    float m_i[2] = {-INFINITY, -INFINITY};
    float l_i[2] = {0.0f, 0.0f};
    float O[8][4];
#pragma unroll
    for (int ni = 0; ni < 8; ++ni)
#pragma unroll
        for (int r = 0; r < 4; ++r) O[ni][r] = 0.0f;

    const int nkt = qBase / 64 + 2;
    for (int kt = 0; kt < nkt; ++kt) {
        const int stg = kt & 1;
        CP_WAIT0();
        __syncthreads();

        if (kt + 1 < nkt) {
            float* Kn = sm + OFF_K + (stg ^ 1) * 64 * AQP;
            float* Vn = sm + OFF_V + (stg ^ 1) * 64 * AVP;
            const float* src = kvK + (size_t)(kt + 1) * 64 * D3;
#pragma unroll
            for (int it = 0; it < 4; ++it) {
                int i = tid + it * 256;
                int r = i >> 4, c4 = (i & 15) * 4;
                cpasync16(&Kn[r * AQP + c4], src + (size_t)r * D3 + c4);
                cpasync16(&Vn[r * AVP + c4], src + DIM + (size_t)r * D3 + c4);
            }
            CP_COMMIT();
        }

        const float* Ks = sm + OFF_K + stg * 64 * AQP;
        const float* Vs = sm + OFF_V + stg * 64 * AVP;
        const int ktBase = kt * 64;

        float sc[8][4];
#pragma unroll
        for (int ni = 0; ni < 8; ++ni)
#pragma unroll
            for (int r = 0; r < 4; ++r) sc[ni][r] = 0.0f;

#pragma unroll
        for (int kk = 0; kk < 8; ++kk) {
            int kb8 = kk * 8;
#pragma unroll
            for (int ni = 0; ni < 8; ++ni) {
                uint32_t bb[2];
                bb[0] = __float_as_uint(Ks[(ni * 8 + g) * AQP + kb8 + t4    ]);
                bb[1] = __float_as_uint(Ks[(ni * 8 + g) * AQP + kb8 + t4 + 4]);
                mma_tf32(sc[ni], qf[kk], bb);
            }
        }

        if (ktBase + 63 > qBase + wrow) {
            const int r0 = qBase + wrow + g;
            const int r1 = r0 + 8;
#pragma unroll
            for (int ni = 0; ni < 8; ++ni) {
                int c0 = ktBase + ni * 8 + t4 * 2;
                int c1 = c0 + 1;
                if (c0 > r0) sc[ni][0] = -1e30f;
                if (c1 > r0) sc[ni][1] = -1e30f;
                if (c0 > r1) sc[ni][2] = -1e30f;
                if (c1 > r1) sc[ni][3] = -1e30f;
            }
        }

#pragma unroll
        for (int hrow = 0; hrow < 2; ++hrow) {
            const int i0 = hrow * 2, i1 = hrow * 2 + 1;
            float tm = -INFINITY;
#pragma unroll
            for (int ni = 0; ni < 8; ++ni)
                tm = fmaxf(tm, fmaxf(sc[ni][i0], sc[ni][i1]));
            tm = fmaxf(tm, __shfl_xor_sync(0xffffffffu, tm, 1, 4));
            tm = fmaxf(tm, __shfl_xor_sync(0xffffffffu, tm, 2, 4));
            float m_new = fmaxf(m_i[hrow], tm);
            float alpha = exp2f(m_i[hrow] - m_new);
            float rs = 0.0f;
#pragma unroll
            for (int ni = 0; ni < 8; ++ni) {
                sc[ni][i0] = exp2f(sc[ni][i0] - m_new);
                sc[ni][i1] = exp2f(sc[ni][i1] - m_new);
                rs += sc[ni][i0] + sc[ni][i1];
            }
            rs += __shfl_xor_sync(0xffffffffu, rs, 1, 4);
            rs += __shfl_xor_sync(0xffffffffu, rs, 2, 4);
            l_i[hrow] = l_i[hrow] * alpha + rs;
            m_i[hrow] = m_new;
#pragma unroll
            for (int ni = 0; ni < 8; ++ni) {
                O[ni][i0] *= alpha;
                O[ni][i1] *= alpha;
            }
        }

#pragma unroll
        for (int ni = 0; ni < 8; ++ni) {
            QP[(wrow + g    ) * AQP + ni * 8 + t4 * 2    ] = tf32f(sc[ni][0]);
            QP[(wrow + g    ) * AQP + ni * 8 + t4 * 2 + 1] = tf32f(sc[ni][1]);
            QP[(wrow + g + 8) * AQP + ni * 8 + t4 * 2    ] = tf32f(sc[ni][2]);
            QP[(wrow + g + 8) * AQP + ni * 8 + t4 * 2 + 1] = tf32f(sc[ni][3]);
        }
        __syncwarp();

#pragma unroll
        for (int kk = 0; kk < 8; ++kk) {
            int kb8 = kk * 8;
            uint32_t a[4];
            a[0] = __float_as_uint(QP[(wrow + g    ) * AQP + kb8 + t4    ]);
            a[1] = __float_as_uint(QP[(wrow + g + 8) * AQP + kb8 + t4    ]);
            a[2] = __float_as_uint(QP[(wrow + g    ) * AQP + kb8 + t4 + 4]);
            a[3] = __float_as_uint(QP[(wrow + g + 8) * AQP + kb8 + t4 + 4]);
#pragma unroll
            for (int ni = 0; ni < 8; ++ni) {
                uint32_t bb[2];
                bb[0] = __float_as_uint(Vs[(kb8 + t4    ) * AVP + ni * 8 + g]);
                bb[1] = __float_as_uint(Vs[(kb8 + t4 + 4) * AVP + ni * 8 + g]);
                mma_tf32(O[ni], a, bb);
            }
        }
    }

    // Epilogue: normalize, tf32-round, write d-PERMUTED (feeds k-perm out-GEMM)
    float* ob = att + (size_t)(b * SEQ + qBase + wrow) * DIM + h * HD;
    const float inv0 = 1.0f / l_i[0];
    const float inv1 = 1.0f / l_i[1];
#pragma unroll
    for (int ni = 0; ni < 8; ++ni) {
        int c0 = ni * 8 + t4 * 2;
        int pbase = (c0 & ~31) + 16 * (t4 & 1) + 2 * (ni & 3) + (t4 >> 1);
        ob[(size_t)g * DIM + pbase]           = tf32f(O[ni][0] * inv0);
        ob[(size_t)g * DIM + pbase + 8]       = tf32f(O[ni][1] * inv0);
        ob[(size_t)(g + 8) * DIM + pbase]     = tf32f(O[ni][2] * inv1);
        ob[(size_t)(g + 8) * DIM + pbase + 8] = tf32f(O[ni][3] * inv1);
    }
}

// ---------------------------------------------------------------------------
extern "C" void kernel_launch(void* const* d_in, const int* in_sizes, int n_in,
                              void* d_out, int out_size)
{
    const float* x     = (const float*)d_in[0];
    const float* w_qkv = (const float*)d_in[1];
    const float* b_qkv = (const float*)d_in[2];
    const float* w_out = (const float*)d_in[3];
    const float* b_out = (const float*)d_in[4];
    float* out = (float*)d_out;

    float *qkv_p, *att_p, *x_p, *w1_p, *w2_p;
    cudaGetSymbolAddress((void**)&qkv_p, g_qkv);
    cudaGetSymbolAddress((void**)&att_p, g_att);
    cudaGetSymbolAddress((void**)&x_p,   g_x);
    cudaGetSymbolAddress((void**)&w1_p,  g_w1);
    cudaGetSymbolAddress((void**)&w2_p,  g_w2);

    // 0) Pre-round + permute inputs
    round_perm<<<1024, 256>>>(x, x_p, (int)((size_t)M_TOT * DIM / 4), DIM);
    transpose_round_perm<<<dim3(D3 / 32, DIM / 32), dim3(32, 8)>>>(w_qkv, w1_p, DIM, D3);
    transpose_round_perm<<<dim3(DIM / 32, DIM / 32), dim3(32, 8)>>>(w_out, w2_p, DIM, DIM);

    const int gemm_smem = 4 * GSTG * (int)sizeof(float);   // 64 KB
    cudaFuncSetAttribute(gemm_tc<1>, cudaFuncAttributeMaxDynamicSharedMemorySize, gemm_smem);
    cudaFuncSetAttribute(gemm_tc<0>, cudaFuncAttributeMaxDynamicSharedMemorySize, gemm_smem);

    // 1) QKV projection (plain tf32-rounded output)
    gemm_tc<1><<<dim3(D3 / 128, M_TOT / 128), 128, gemm_smem>>>(
        x_p, w1_p, b_qkv, qkv_p, M_TOT, D3, DIM);

    // 2) Causal flash attention (writes att d-permuted)
    cudaFuncSetAttribute(attn_fwd_tc, cudaFuncAttributeMaxDynamicSharedMemorySize, ATT_SMEM);
    attn_fwd_tc<<<dim3(SEQ / 128, NH, B_SZ), 256, ATT_SMEM>>>(qkv_p, att_p);

    // 3) Output projection (A = d-permuted att; full fp32 output)
    gemm_tc<0><<<dim3(DIM / 128, M_TOT / 128), 128, gemm_smem>>>(
        att_p, w2_p, b_out, out, M_TOT, DIM, DIM);
}

// round 11
// speedup vs baseline: 1.8197x; 1.5955x over previous
#include <cuda_runtime.h>
#include <cuda_fp16.h>
#include <math.h>
#include <stdint.h>

#define B_SZ 4
#define SEQ  2048
#define DIM  1024
#define NH   16
#define HD   64
#define D3   3072
#define M_TOT (B_SZ * SEQ)

// Scratch (device globals — no runtime allocation allowed)
__device__ __half g_x16 [(size_t)M_TOT * DIM];   // x, fp16
__device__ __half g_w1h [(size_t)DIM * D3];      // w_qkv^T [3072][1024], fp16
__device__ __half g_w2h [(size_t)DIM * DIM];     // w_out^T [1024][1024], fp16
__device__ __half g_qkv [(size_t)M_TOT * D3];    // qkv, fp16
__device__ __half g_vT  [(size_t)B_SZ * NH * HD * SEQ];  // V^T [b,h,d,key], fp16
__device__ __half g_att [(size_t)M_TOT * DIM];   // attention out, fp16

// ---------------------------------------------------------------------------
// Helpers
// ---------------------------------------------------------------------------
__device__ __forceinline__ void mma_f16(float c[4], const uint32_t a[4], const uint32_t b[2]) {
    asm volatile(
        "mma.sync.aligned.m16n8k16.row.col.f32.f16.f16.f32 "
        "{%0,%1,%2,%3}, {%4,%5,%6,%7}, {%8,%9}, {%0,%1,%2,%3};"
        : "+f"(c[0]), "+f"(c[1]), "+f"(c[2]), "+f"(c[3])
        : "r"(a[0]), "r"(a[1]), "r"(a[2]), "r"(a[3]), "r"(b[0]), "r"(b[1]));
}
__device__ __forceinline__ void cpasync16(void* smem, const void* gmem) {
    uint32_t sa = (uint32_t)__cvta_generic_to_shared(smem);
    asm volatile("cp.async.cg.shared.global [%0], [%1], 16;" :: "r"(sa), "l"(gmem));
}
#define CP_COMMIT() asm volatile("cp.async.commit_group;" ::: "memory")
#define CP_WAIT0()  asm volatile("cp.async.wait_all;" ::: "memory")
#define U32(p) (*(const uint32_t*)(p))

// ---------------------------------------------------------------------------
// Pre-kernels
// ---------------------------------------------------------------------------
__global__ __launch_bounds__(256) void round_h(
    const float* __restrict__ in, __half* __restrict__ out, int n4)
{
    int i = blockIdx.x * blockDim.x + threadIdx.x;
    int stride = gridDim.x * blockDim.x;
    for (; i < n4; i += stride) {
        float4 v = ((const float4*)in)[i];
        __half2 a = __floats2half2_rn(v.x, v.y);
        __half2 b = __floats2half2_rn(v.z, v.w);
        uint2 o;
        o.x = *(uint32_t*)&a;
        o.y = *(uint32_t*)&b;
        *(uint2*)&out[(size_t)i * 4] = o;
    }
}

// in [K][N] fp32 -> out [N][K] fp16
__global__ __launch_bounds__(256) void transpose_round_h(
    const float* __restrict__ in, __half* __restrict__ out, int K, int N)
{
    __shared__ float t[32][33];
    const int k0 = blockIdx.y * 32, n0 = blockIdx.x * 32;
    const int tx = threadIdx.x, ty = threadIdx.y;
#pragma unroll
    for (int j = 0; j < 4; ++j)
        t[ty + j * 8][tx] = in[(size_t)(k0 + ty + j * 8) * N + n0 + tx];
    __syncthreads();
#pragma unroll
    for (int j = 0; j < 4; ++j) {
        int row = ty + j * 8;
        out[(size_t)(n0 + row) * K + k0 + tx] = __float2half_rn(t[tx][row]);
    }
}

// V (fp16, qkv cols [2048,3072)) -> vT [b,h,d,key]. Coalesced both sides.
__global__ __launch_bounds__(256) void v_to_vT(
    const __half* __restrict__ qkv, __half* __restrict__ vT)
{
    __shared__ __half t[64 * 66];
    const int key0 = blockIdx.x * 64;
    const int h  = blockIdx.y;
    const int b  = blockIdx.z;
    const int tid = threadIdx.x;
#pragma unroll
    for (int i = 0; i < 8; ++i) {
        int idx = tid + i * 256;
        int key = idx >> 5, w = idx & 31;
        __half2 v = *(const __half2*)&qkv[(size_t)(b * SEQ + key0 + key) * D3
                                          + 2 * DIM + h * HD + w * 2];
        *(__half2*)&t[key * 66 + w * 2] = v;
    }
    __syncthreads();
#pragma unroll
    for (int i = 0; i < 8; ++i) {
        int idx = tid + i * 256;
        int d = idx >> 5, kw = idx & 31;
        __half2 o = __halves2half2(t[(2 * kw) * 66 + d], t[(2 * kw + 1) * 66 + d]);
        *(__half2*)&vT[(((size_t)b * NH + h) * HD + d) * SEQ + key0 + 2 * kw] = o;
    }
}

// ---------------------------------------------------------------------------
// fp16 TC GEMM: C = A@W + bias.  A [M][K] fp16, Wt [N][K] fp16.
// BM=BN=128, BK=32, 256 thr, 8 warps (2x4), warp tile 64x32, m16n8k16.
// SMEM pitch 40 halves (20 words; bank 20g+t4 per phase -> conflict-free).
// 2-stage cp.async, one __syncthreads per iter.
// OUT_HALF=1: C fp16 (intermediate); OUT_HALF=0: C fp32 (final).
// ---------------------------------------------------------------------------
#define HP 40
#define HSTG (128 * HP)          // halves per operand stage (5120)
#define GSMEM (4 * HSTG * 2)     // bytes: 2 stages x (A+B) = 40960

template<int OUT_HALF>
__global__ __launch_bounds__(256, 2) void gemm_h(
    const __half* __restrict__ A, const __half* __restrict__ Wt,
    const float* __restrict__ bias, void* __restrict__ Cout,
    int M, int N, int K)
{
    extern __shared__ __half hsm[];

    const int tid  = threadIdx.x;
    const int lane = tid & 31;
    const int warp = tid >> 5;
    const int warpM = warp >> 2;      // 0..1
    const int warpN = warp & 3;       // 0..3
    const int g  = lane >> 2;
    const int t4 = lane & 3;
    const int mBase = blockIdx.y * 128;
    const int nBase = blockIdx.x * 128;

    // cp.async coords: 512 chunks per operand tile, 2 per thread
    int row_[2], c8_[2];
#pragma unroll
    for (int f = 0; f < 2; ++f) {
        int idx = tid + f * 256;
        row_[f] = idx >> 2;
        c8_[f]  = (idx & 3) * 8;     // half offset of 16B chunk
    }

    float acc[4][4][4];
#pragma unroll
    for (int mi = 0; mi < 4; ++mi)
#pragma unroll
        for (int ni = 0; ni < 4; ++ni)
#pragma unroll
            for (int r = 0; r < 4; ++r) acc[mi][ni][r] = 0.0f;

    auto loadStage = [&](int s, int k0) {
        __half* As = hsm + s * 2 * HSTG;
        __half* Bs = As + HSTG;
#pragma unroll
        for (int f = 0; f < 2; ++f) {
            int so = row_[f] * HP + c8_[f];
            cpasync16(&As[so], &A [(size_t)(mBase + row_[f]) * K + k0 + c8_[f]]);
            cpasync16(&Bs[so], &Wt[(size_t)(nBase + row_[f]) * K + k0 + c8_[f]]);
        }
    };

    loadStage(0, 0);
    CP_COMMIT();

    int stage = 0;
    for (int k0 = 0; k0 < K; k0 += 32) {
        CP_WAIT0();
        __syncthreads();

        if (k0 + 32 < K) {
            loadStage(stage ^ 1, k0 + 32);
            CP_COMMIT();
        }

        const __half* As = hsm + stage * 2 * HSTG;
        const __half* Bs = As + HSTG;
#pragma unroll
        for (int s = 0; s < 2; ++s) {
            const int ko = s * 16 + 2 * t4;
            uint32_t bfr[4][2];
#pragma unroll
            for (int ni = 0; ni < 4; ++ni) {
                int n = warpN * 32 + ni * 8 + g;
                bfr[ni][0] = U32(&Bs[n * HP + ko]);
                bfr[ni][1] = U32(&Bs[n * HP + ko + 8]);
            }
#pragma unroll
            for (int mi = 0; mi < 4; ++mi) {
                int m = warpM * 64 + mi * 16;
                uint32_t a[4];
                a[0] = U32(&As[(m + g    ) * HP + ko]);
                a[1] = U32(&As[(m + g + 8) * HP + ko]);
                a[2] = U32(&As[(m + g    ) * HP + ko + 8]);
                a[3] = U32(&As[(m + g + 8) * HP + ko + 8]);
#pragma unroll
                for (int ni = 0; ni < 4; ++ni)
                    mma_f16(acc[mi][ni], a, bfr[ni]);
            }
        }
        stage ^= 1;
    }

    // Epilogue
#pragma unroll
    for (int mi = 0; mi < 4; ++mi) {
        int row0 = mBase + warpM * 64 + mi * 16 + g;
#pragma unroll
        for (int ni = 0; ni < 4; ++ni) {
            int col = nBase + warpN * 32 + ni * 8 + 2 * t4;
            float2 bv = *(const float2*)&bias[col];
            float v00 = acc[mi][ni][0] + bv.x;
            float v01 = acc[mi][ni][1] + bv.y;
            float v10 = acc[mi][ni][2] + bv.x;
            float v11 = acc[mi][ni][3] + bv.y;
            if (OUT_HALF) {
                __half* C = (__half*)Cout;
                __half2 o0 = __floats2half2_rn(v00, v01);
                __half2 o1 = __floats2half2_rn(v10, v11);
                *(__half2*)&C[(size_t)row0 * N + col]       = o0;
                *(__half2*)&C[(size_t)(row0 + 8) * N + col] = o1;
            } else {
                float* C = (float*)Cout;
                float2 o0 = {v00, v01};
                float2 o1 = {v10, v11};
                *(float2*)&C[(size_t)row0 * N + col]       = o0;
                *(float2*)&C[(size_t)(row0 + 8) * N + col] = o1;
            }
        }
    }
}

// ---------------------------------------------------------------------------
// Causal flash attention, fp16 MMA, fp32 softmax/accum.
// CTA: 256 thr (8 warps), Q tile 128 rows, K/V tiles 64 keys.
// Q unscaled in MMA; scale*log2(e) applied in fp32 after MMA.
// Q frags hoisted to regs; P aliases Q smem; V consumed as V^T [d][key].
// NOTE: fp16 64x64 tile = 512 x 16B chunks -> K/V load loops are it<2.
// ---------------------------------------------------------------------------
#define AQP 72   // halves pitch (36 words -> bank 4g+t4, conflict-free)
#define OFF_K (128 * AQP)
#define OFF_V (OFF_K + 2 * 64 * AQP)
#define ATT_SMEM ((OFF_V + 2 * 64 * AQP) * 2)   // bytes (55296)
#define ASCALE 0.1803368801111244f              // 0.125 * log2(e)

__global__ __launch_bounds__(256, 2) void attn_fwd_h(
    const __half* __restrict__ qkv, const __half* __restrict__ vT,
    __half* __restrict__ att)
{
    extern __shared__ __half hsm[];
    __half* QP = hsm;    // Q tile; rows [wrow,wrow+16) later reused for P

    const int qt = gridDim.x - 1 - blockIdx.x;   // longest-first
    const int h  = blockIdx.y;
    const int b  = blockIdx.z;
    const int qBase = qt * 128;
    const int tid  = threadIdx.x;
    const int lane = tid & 31;
    const int warp = tid >> 5;
    const int g  = lane >> 2;
    const int t4 = lane & 3;
    const int wrow = warp * 16;

    const __half* kvK = qkv + (size_t)(b * SEQ) * D3 + DIM + h * HD;
    const __half* vtb = vT + (((size_t)b * NH + h) * HD) * SEQ;
    const __half* qb  = qkv + (size_t)(b * SEQ + qBase) * D3 + h * HD;

    // prefetch K/V tile 0 (512 chunks each) + Q (1024 chunks)
    {
        __half* Ks = hsm + OFF_K;
        __half* Vs = hsm + OFF_V;
#pragma unroll
        for (int it = 0; it < 2; ++it) {
            int i = tid + it * 256;
            int r = i >> 3, c8 = (i & 7) * 8;       // r in [0,64)
            cpasync16(&Ks[r * AQP + c8], kvK + (size_t)r * D3 + c8);
            cpasync16(&Vs[r * AQP + c8], vtb + (size_t)r * SEQ + c8);
        }
#pragma unroll
        for (int it = 0; it < 4; ++it) {
            int i = tid + it * 256;
            int r = i >> 3, c8 = (i & 7) * 8;       // r in [0,128) for Q
            cpasync16(&QP[r * AQP + c8], qb + (size_t)r * D3 + c8);
        }
        CP_COMMIT();
    }
    CP_WAIT0();
    __syncthreads();

    // Hoist Q fragments (4 k16 steps x 4 regs); QP rows become warp-private P
    uint32_t qf[4][4];
#pragma unroll
    for (int s = 0; s < 4; ++s) {
        const int ko = s * 16 + 2 * t4;
        qf[s][0] = U32(&QP[(wrow + g    ) * AQP + ko]);
        qf[s][1] = U32(&QP[(wrow + g + 8) * AQP + ko]);
        qf[s][2] = U32(&QP[(wrow + g    ) * AQP + ko + 8]);
        qf[s][3] = U32(&QP[(wrow + g + 8) * AQP + ko + 8]);
    }

    float m_i[2] = {-INFINITY, -INFINITY};
    float l_i[2] = {0.0f, 0.0f};
    float O[8][4];
#pragma unroll
    for (int ni = 0; ni < 8; ++ni)
#pragma unroll
        for (int r = 0; r < 4; ++r) O[ni][r] = 0.0f;

    const int nkt = qBase / 64 + 2;
    for (int kt = 0; kt < nkt; ++kt) {
        const int stg = kt & 1;
        CP_WAIT0();
        __syncthreads();

        if (kt + 1 < nkt) {
            __half* Kn = hsm + OFF_K + (stg ^ 1) * 64 * AQP;
            __half* Vn = hsm + OFF_V + (stg ^ 1) * 64 * AQP;
            const __half* srcK = kvK + (size_t)(kt + 1) * 64 * D3;
            const __half* srcV = vtb + (kt + 1) * 64;
#pragma unroll
            for (int it = 0; it < 2; ++it) {
                int i = tid + it * 256;
                int r = i >> 3, c8 = (i & 7) * 8;   // r in [0,64)
                cpasync16(&Kn[r * AQP + c8], srcK + (size_t)r * D3 + c8);
                cpasync16(&Vn[r * AQP + c8], srcV + (size_t)r * SEQ + c8);
            }
            CP_COMMIT();
        }

        const __half* Ks = hsm + OFF_K + stg * 64 * AQP;
        const __half* Vs = hsm + OFF_V + stg * 64 * AQP;
        const int ktBase = kt * 64;

        // S = Q K^T (raw)
        float sc[8][4];
#pragma unroll
        for (int ni = 0; ni < 8; ++ni)
#pragma unroll
            for (int r = 0; r < 4; ++r) sc[ni][r] = 0.0f;

#pragma unroll
        for (int s = 0; s < 4; ++s) {
            const int ko = s * 16 + 2 * t4;
#pragma unroll
            for (int ni = 0; ni < 8; ++ni) {
                uint32_t bb[2];
                bb[0] = U32(&Ks[(ni * 8 + g) * AQP + ko]);
                bb[1] = U32(&Ks[(ni * 8 + g) * AQP + ko + 8]);
                mma_f16(sc[ni], qf[s], bb);
            }
        }

        // scale (exact fp32) then causal mask
#pragma unroll
        for (int ni = 0; ni < 8; ++ni)
#pragma unroll
            for (int r = 0; r < 4; ++r) sc[ni][r] *= ASCALE;

        if (ktBase + 63 > qBase + wrow) {
            const int r0 = qBase + wrow + g;
            const int r1 = r0 + 8;
#pragma unroll
            for (int ni = 0; ni < 8; ++ni) {
                int c0 = ktBase + ni * 8 + 2 * t4;
                int c1 = c0 + 1;
                if (c0 > r0) sc[ni][0] = -1e30f;
                if (c1 > r0) sc[ni][1] = -1e30f;
                if (c0 > r1) sc[ni][2] = -1e30f;
                if (c1 > r1) sc[ni][3] = -1e30f;
            }
        }

        // Online softmax (base-2), quad-reduce
#pragma unroll
        for (int hrow = 0; hrow < 2; ++hrow) {
            const int i0 = hrow * 2, i1 = hrow * 2 + 1;
            float tm = -INFINITY;
#pragma unroll
            for (int ni = 0; ni < 8; ++ni)
                tm = fmaxf(tm, fmaxf(sc[ni][i0], sc[ni][i1]));
            tm = fmaxf(tm, __shfl_xor_sync(0xffffffffu, tm, 1, 4));
            tm = fmaxf(tm, __shfl_xor_sync(0xffffffffu, tm, 2, 4));
            float m_new = fmaxf(m_i[hrow], tm);
            float alpha = exp2f(m_i[hrow] - m_new);
            float rs = 0.0f;
#pragma unroll
            for (int ni = 0; ni < 8; ++ni) {
                sc[ni][i0] = exp2f(sc[ni][i0] - m_new);
                sc[ni][i1] = exp2f(sc[ni][i1] - m_new);
                rs += sc[ni][i0] + sc[ni][i1];
            }
            rs += __shfl_xor_sync(0xffffffffu, rs, 1, 4);
            rs += __shfl_xor_sync(0xffffffffu, rs, 2, 4);
            l_i[hrow] = l_i[hrow] * alpha + rs;
            m_i[hrow] = m_new;
#pragma unroll
            for (int ni = 0; ni < 8; ++ni) {
                O[ni][i0] *= alpha;
                O[ni][i1] *= alpha;
            }
        }

        // P -> QP smem as fp16 (half2 stores, warp-private rows)
#pragma unroll
        for (int ni = 0; ni < 8; ++ni) {
            __half2 p0 = __floats2half2_rn(sc[ni][0], sc[ni][1]);
            __half2 p1 = __floats2half2_rn(sc[ni][2], sc[ni][3]);
            *(__half2*)&QP[(wrow + g    ) * AQP + ni * 8 + 2 * t4] = p0;
            *(__half2*)&QP[(wrow + g + 8) * AQP + ni * 8 + 2 * t4] = p1;
        }
        __syncwarp();

        // O += P @ V  (B from V^T [d][key] -> contiguous key pairs)
#pragma unroll
        for (int s = 0; s < 4; ++s) {
            const int ko = s * 16 + 2 * t4;
            uint32_t a[4];
            a[0] = U32(&QP[(wrow + g    ) * AQP + ko]);
            a[1] = U32(&QP[(wrow + g + 8) * AQP + ko]);
            a[2] = U32(&QP[(wrow + g    ) * AQP + ko + 8]);
            a[3] = U32(&QP[(wrow + g + 8) * AQP + ko + 8]);
#pragma unroll
            for (int ni = 0; ni < 8; ++ni) {
                uint32_t bb[2];
                bb[0] = U32(&Vs[(ni * 8 + g) * AQP + ko]);
                bb[1] = U32(&Vs[(ni * 8 + g) * AQP + ko + 8]);
                mma_f16(O[ni], a, bb);
            }
        }
    }

    // Epilogue: normalize, fp16, plain layout
    __half* ob = att + (size_t)(b * SEQ + qBase + wrow) * DIM + h * HD;
    const float inv0 = 1.0f / l_i[0];
    const float inv1 = 1.0f / l_i[1];
#pragma unroll
    for (int ni = 0; ni < 8; ++ni) {
        int col = ni * 8 + 2 * t4;
        __half2 o0 = __floats2half2_rn(O[ni][0] * inv0, O[ni][1] * inv0);
        __half2 o1 = __floats2half2_rn(O[ni][2] * inv1, O[ni][3] * inv1);
        *(__half2*)(ob + (size_t)(g    ) * DIM + col) = o0;
        *(__half2*)(ob + (size_t)(g + 8) * DIM + col) = o1;
    }
}

// ---------------------------------------------------------------------------
extern "C" void kernel_launch(void* const* d_in, const int* in_sizes, int n_in,
                              void* d_out, int out_size)
{
    const float* x     = (const float*)d_in[0];
    const float* w_qkv = (const float*)d_in[1];
    const float* b_qkv = (const float*)d_in[2];
    const float* w_out = (const float*)d_in[3];
    const float* b_out = (const float*)d_in[4];
    float* out = (float*)d_out;

    __half *x16, *w1h, *w2h, *qkv16, *vT16, *att16;
    cudaGetSymbolAddress((void**)&x16,   g_x16);
    cudaGetSymbolAddress((void**)&w1h,   g_w1h);
    cudaGetSymbolAddress((void**)&w2h,   g_w2h);
    cudaGetSymbolAddress((void**)&qkv16, g_qkv);
    cudaGetSymbolAddress((void**)&vT16,  g_vT);
    cudaGetSymbolAddress((void**)&att16, g_att);

    // 0) Convert inputs to fp16 (x plain; weights transposed to [N][K])
    round_h<<<512, 256>>>(x, x16, (int)((size_t)M_TOT * DIM / 4));
    transpose_round_h<<<dim3(D3 / 32, DIM / 32), dim3(32, 8)>>>(w_qkv, w1h, DIM, D3);
    transpose_round_h<<<dim3(DIM / 32, DIM / 32), dim3(32, 8)>>>(w_out, w2h, DIM, DIM);

    cudaFuncSetAttribute(gemm_h<1>, cudaFuncAttributeMaxDynamicSharedMemorySize, GSMEM);
    cudaFuncSetAttribute(gemm_h<0>, cudaFuncAttributeMaxDynamicSharedMemorySize, GSMEM);

    // 1) QKV projection (fp16 out)
    gemm_h<1><<<dim3(D3 / 128, M_TOT / 128), 256, GSMEM>>>(
        x16, w1h, b_qkv, qkv16, M_TOT, D3, DIM);

    // 1b) V -> V^T [b,h,d,key]
    v_to_vT<<<dim3(SEQ / 64, NH, B_SZ), 256>>>(qkv16, vT16);

    // 2) Causal flash attention (fp16 MMA)
    cudaFuncSetAttribute(attn_fwd_h, cudaFuncAttributeMaxDynamicSharedMemorySize, ATT_SMEM);
    attn_fwd_h<<<dim3(SEQ / 128, NH, B_SZ), 256, ATT_SMEM>>>(qkv16, vT16, att16);

    // 3) Output projection (fp32 out)
    gemm_h<0><<<dim3(DIM / 128, M_TOT / 128), 256, GSMEM>>>(
        att16, w2h, b_out, out, M_TOT, DIM, DIM);
}

// round 12
// speedup vs baseline: 1.8596x; 1.0219x over previous
#include <cuda_runtime.h>
#include <cuda_fp16.h>
#include <math.h>
#include <stdint.h>

#define B_SZ 4
#define SEQ  2048
#define DIM  1024
#define NH   16
#define HD   64
#define D3   3072
#define M_TOT (B_SZ * SEQ)

// Scratch (device globals — no runtime allocation allowed)
__device__ __half g_x16 [(size_t)M_TOT * DIM];   // x, fp16
__device__ __half g_w1h [(size_t)DIM * D3];      // w_qkv^T [3072][1024], fp16
__device__ __half g_w2h [(size_t)DIM * DIM];     // w_out^T [1024][1024], fp16
__device__ __half g_qkv [(size_t)M_TOT * D3];    // qkv, fp16
__device__ __half g_vT  [(size_t)B_SZ * NH * HD * SEQ];  // V^T [b,h,d,key], fp16
__device__ __half g_att [(size_t)M_TOT * DIM];   // attention out, fp16

// ---------------------------------------------------------------------------
// Helpers
// ---------------------------------------------------------------------------
__device__ __forceinline__ void mma_f16(float c[4], const uint32_t a[4], const uint32_t b[2]) {
    asm volatile(
        "mma.sync.aligned.m16n8k16.row.col.f32.f16.f16.f32 "
        "{%0,%1,%2,%3}, {%4,%5,%6,%7}, {%8,%9}, {%0,%1,%2,%3};"
        : "+f"(c[0]), "+f"(c[1]), "+f"(c[2]), "+f"(c[3])
        : "r"(a[0]), "r"(a[1]), "r"(a[2]), "r"(a[3]), "r"(b[0]), "r"(b[1]));
}
__device__ __forceinline__ void cpasync16(void* smem, const void* gmem) {
    uint32_t sa = (uint32_t)__cvta_generic_to_shared(smem);
    asm volatile("cp.async.cg.shared.global [%0], [%1], 16;" :: "r"(sa), "l"(gmem));
}
#define CP_COMMIT()  asm volatile("cp.async.commit_group;" ::: "memory")
#define CP_WAIT0()   asm volatile("cp.async.wait_all;" ::: "memory")
#define CP_WAITG1()  asm volatile("cp.async.wait_group 1;" ::: "memory")
#define U32(p) (*(const uint32_t*)(p))

// ---------------------------------------------------------------------------
// Pre-kernels
// ---------------------------------------------------------------------------
__global__ __launch_bounds__(256) void round_h(
    const float* __restrict__ in, __half* __restrict__ out, int n4)
{
    int i = blockIdx.x * blockDim.x + threadIdx.x;
    int stride = gridDim.x * blockDim.x;
    for (; i < n4; i += stride) {
        float4 v = ((const float4*)in)[i];
        __half2 a = __floats2half2_rn(v.x, v.y);
        __half2 b = __floats2half2_rn(v.z, v.w);
        uint2 o;
        o.x = *(uint32_t*)&a;
        o.y = *(uint32_t*)&b;
        *(uint2*)&out[(size_t)i * 4] = o;
    }
}

// in [K][N] fp32 -> out [N][K] fp16
__global__ __launch_bounds__(256) void transpose_round_h(
    const float* __restrict__ in, __half* __restrict__ out, int K, int N)
{
    __shared__ float t[32][33];
    const int k0 = blockIdx.y * 32, n0 = blockIdx.x * 32;
    const int tx = threadIdx.x, ty = threadIdx.y;
#pragma unroll
    for (int j = 0; j < 4; ++j)
        t[ty + j * 8][tx] = in[(size_t)(k0 + ty + j * 8) * N + n0 + tx];
    __syncthreads();
#pragma unroll
    for (int j = 0; j < 4; ++j) {
        int row = ty + j * 8;
        out[(size_t)(n0 + row) * K + k0 + tx] = __float2half_rn(t[tx][row]);
    }
}

// V (fp16, qkv cols [2048,3072)) -> vT [b,h,d,key]. Coalesced both sides.
__global__ __launch_bounds__(256) void v_to_vT(
    const __half* __restrict__ qkv, __half* __restrict__ vT)
{
    __shared__ __half t[64 * 66];
    const int key0 = blockIdx.x * 64;
    const int h  = blockIdx.y;
    const int b  = blockIdx.z;
    const int tid = threadIdx.x;
#pragma unroll
    for (int i = 0; i < 8; ++i) {
        int idx = tid + i * 256;
        int key = idx >> 5, w = idx & 31;
        __half2 v = *(const __half2*)&qkv[(size_t)(b * SEQ + key0 + key) * D3
                                          + 2 * DIM + h * HD + w * 2];
        *(__half2*)&t[key * 66 + w * 2] = v;
    }
    __syncthreads();
#pragma unroll
    for (int i = 0; i < 8; ++i) {
        int idx = tid + i * 256;
        int d = idx >> 5, kw = idx & 31;
        __half2 o = __halves2half2(t[(2 * kw) * 66 + d], t[(2 * kw + 1) * 66 + d]);
        *(__half2*)&vT[(((size_t)b * NH + h) * HD + d) * SEQ + key0 + 2 * kw] = o;
    }
}

// ---------------------------------------------------------------------------
// fp16 TC GEMM: C = A@W + bias.  A [M][K] fp16, Wt [N][K] fp16.
// BM=BN=128, BK=32, 256 thr, 8 warps (2x4), warp tile 64x32, m16n8k16.
// SMEM pitch 40 halves; THREE-stage cp.async pipeline with wait_group 1
// (two compute phases of latency hiding).
// OUT_HALF=1: C fp16 (intermediate); OUT_HALF=0: C fp32 (final).
// ---------------------------------------------------------------------------
#define HP 40
#define HSTG (128 * HP)            // halves per operand stage (5120)
#define GSMEM (6 * HSTG * 2)       // bytes: 3 stages x (A+B) = 61440

template<int OUT_HALF>
__global__ __launch_bounds__(256, 2) void gemm_h(
    const __half* __restrict__ A, const __half* __restrict__ Wt,
    const float* __restrict__ bias, void* __restrict__ Cout,
    int M, int N, int K)
{
    extern __shared__ __half hsm[];

    const int tid  = threadIdx.x;
    const int lane = tid & 31;
    const int warp = tid >> 5;
    const int warpM = warp >> 2;      // 0..1
    const int warpN = warp & 3;       // 0..3
    const int g  = lane >> 2;
    const int t4 = lane & 3;
    const int mBase = blockIdx.y * 128;
    const int nBase = blockIdx.x * 128;

    // cp.async coords: 512 chunks per operand tile, 2 per thread
    int row_[2], c8_[2];
#pragma unroll
    for (int f = 0; f < 2; ++f) {
        int idx = tid + f * 256;
        row_[f] = idx >> 2;
        c8_[f]  = (idx & 3) * 8;     // half offset of 16B chunk
    }

    float acc[4][4][4];
#pragma unroll
    for (int mi = 0; mi < 4; ++mi)
#pragma unroll
        for (int ni = 0; ni < 4; ++ni)
#pragma unroll
            for (int r = 0; r < 4; ++r) acc[mi][ni][r] = 0.0f;

    auto loadStage = [&](int s, int k0) {
        __half* As = hsm + s * 2 * HSTG;
        __half* Bs = As + HSTG;
#pragma unroll
        for (int f = 0; f < 2; ++f) {
            int so = row_[f] * HP + c8_[f];
            cpasync16(&As[so], &A [(size_t)(mBase + row_[f]) * K + k0 + c8_[f]]);
            cpasync16(&Bs[so], &Wt[(size_t)(nBase + row_[f]) * K + k0 + c8_[f]]);
        }
    };

    // prologue: stages 0 and 1 in flight
    loadStage(0, 0);
    CP_COMMIT();
    loadStage(1, 32);
    CP_COMMIT();

    const int nIter = K / 32;
    for (int i = 0; i < nIter; ++i) {
        const int s = i % 3;
        CP_WAITG1();          // stage i done; stage i+1 may still be in flight
        __syncthreads();      // all warps finished reading stage (i+2)%3

        if (i + 2 < nIter)
            loadStage((i + 2) % 3, (i + 2) * 32);
        CP_COMMIT();          // always commit (possibly empty) to keep ordering

        const __half* As = hsm + s * 2 * HSTG;
        const __half* Bs = As + HSTG;
#pragma unroll
        for (int ss = 0; ss < 2; ++ss) {
            const int ko = ss * 16 + 2 * t4;
            uint32_t bfr[4][2];
#pragma unroll
            for (int ni = 0; ni < 4; ++ni) {
                int n = warpN * 32 + ni * 8 + g;
                bfr[ni][0] = U32(&Bs[n * HP + ko]);
                bfr[ni][1] = U32(&Bs[n * HP + ko + 8]);
            }
#pragma unroll
            for (int mi = 0; mi < 4; ++mi) {
                int m = warpM * 64 + mi * 16;
                uint32_t a[4];
                a[0] = U32(&As[(m + g    ) * HP + ko]);
                a[1] = U32(&As[(m + g + 8) * HP + ko]);
                a[2] = U32(&As[(m + g    ) * HP + ko + 8]);
                a[3] = U32(&As[(m + g + 8) * HP + ko + 8]);
#pragma unroll
                for (int ni = 0; ni < 4; ++ni)
                    mma_f16(acc[mi][ni], a, bfr[ni]);
            }
        }
    }

    // Epilogue
#pragma unroll
    for (int mi = 0; mi < 4; ++mi) {
        int row0 = mBase + warpM * 64 + mi * 16 + g;
#pragma unroll
        for (int ni = 0; ni < 4; ++ni) {
            int col = nBase + warpN * 32 + ni * 8 + 2 * t4;
            float2 bv = *(const float2*)&bias[col];
            float v00 = acc[mi][ni][0] + bv.x;
            float v01 = acc[mi][ni][1] + bv.y;
            float v10 = acc[mi][ni][2] + bv.x;
            float v11 = acc[mi][ni][3] + bv.y;
            if (OUT_HALF) {
                __half* C = (__half*)Cout;
                __half2 o0 = __floats2half2_rn(v00, v01);
                __half2 o1 = __floats2half2_rn(v10, v11);
                *(__half2*)&C[(size_t)row0 * N + col]       = o0;
                *(__half2*)&C[(size_t)(row0 + 8) * N + col] = o1;
            } else {
                float* C = (float*)Cout;
                float2 o0 = {v00, v01};
                float2 o1 = {v10, v11};
                *(float2*)&C[(size_t)row0 * N + col]       = o0;
                *(float2*)&C[(size_t)(row0 + 8) * N + col] = o1;
            }
        }
    }
}

// ---------------------------------------------------------------------------
// Causal flash attention, fp16 MMA, fp32 softmax/accum.
// CTA: 256 thr (8 warps), Q tile 128 rows, K/V tiles 64 keys.
// THREE-stage K/V cp.async pipeline (wait_group 1).
// Q frags hoisted to regs; P aliases Q smem; V consumed as V^T [d][key].
// ---------------------------------------------------------------------------
#define AQP 72   // halves pitch (36 words -> bank 4g+t4, conflict-free)
#define KSTG (64 * AQP)                        // halves per K (or V) stage
#define OFF_K (128 * AQP)                      // after Q/P tile
#define OFF_V (OFF_K + 3 * KSTG)
#define ATT_SMEM ((OFF_V + 3 * KSTG) * 2)      // bytes (73728)
#define ASCALE 0.1803368801111244f             // 0.125 * log2(e)

__global__ __launch_bounds__(256, 2) void attn_fwd_h(
    const __half* __restrict__ qkv, const __half* __restrict__ vT,
    __half* __restrict__ att)
{
    extern __shared__ __half hsm[];
    __half* QP = hsm;    // Q tile; rows [wrow,wrow+16) later reused for P

    const int qt = gridDim.x - 1 - blockIdx.x;   // longest-first
    const int h  = blockIdx.y;
    const int b  = blockIdx.z;
    const int qBase = qt * 128;
    const int tid  = threadIdx.x;
    const int lane = tid & 31;
    const int warp = tid >> 5;
    const int g  = lane >> 2;
    const int t4 = lane & 3;
    const int wrow = warp * 16;

    const __half* kvK = qkv + (size_t)(b * SEQ) * D3 + DIM + h * HD;
    const __half* vtb = vT + (((size_t)b * NH + h) * HD) * SEQ;
    const __half* qb  = qkv + (size_t)(b * SEQ + qBase) * D3 + h * HD;

    const int nkt = qBase / 64 + 2;   // >= 2 always

    auto loadKV = [&](int s, int kt) {
        __half* Ks = hsm + OFF_K + s * KSTG;
        __half* Vs = hsm + OFF_V + s * KSTG;
        const __half* srcK = kvK + (size_t)kt * 64 * D3;
        const __half* srcV = vtb + kt * 64;
#pragma unroll
        for (int it = 0; it < 2; ++it) {
            int i = tid + it * 256;
            int r = i >> 3, c8 = (i & 7) * 8;     // r in [0,64)
            cpasync16(&Ks[r * AQP + c8], srcK + (size_t)r * D3 + c8);
            cpasync16(&Vs[r * AQP + c8], srcV + (size_t)r * SEQ + c8);
        }
    };

    // prologue: group0 = Q + KV tile 0; group1 = KV tile 1
    {
#pragma unroll
        for (int it = 0; it < 4; ++it) {
            int i = tid + it * 256;
            int r = i >> 3, c8 = (i & 7) * 8;     // r in [0,128) for Q
            cpasync16(&QP[r * AQP + c8], qb + (size_t)r * D3 + c8);
        }
        loadKV(0, 0);
        CP_COMMIT();
        loadKV(1, 1);
        CP_COMMIT();
    }

    // Wait for Q (group0) then hoist Q fragments
    CP_WAITG1();
    __syncthreads();
    uint32_t qf[4][4];
#pragma unroll
    for (int s = 0; s < 4; ++s) {
        const int ko = s * 16 + 2 * t4;
        qf[s][0] = U32(&QP[(wrow + g    ) * AQP + ko]);
        qf[s][1] = U32(&QP[(wrow + g + 8) * AQP + ko]);
        qf[s][2] = U32(&QP[(wrow + g    ) * AQP + ko + 8]);
        qf[s][3] = U32(&QP[(wrow + g + 8) * AQP + ko + 8]);
    }

    float m_i[2] = {-INFINITY, -INFINITY};
    float l_i[2] = {0.0f, 0.0f};
    float O[8][4];
#pragma unroll
    for (int ni = 0; ni < 8; ++ni)
#pragma unroll
        for (int r = 0; r < 4; ++r) O[ni][r] = 0.0f;

    for (int kt = 0; kt < nkt; ++kt) {
        const int stg = kt % 3;
        CP_WAITG1();          // KV tile kt resident; kt+1 may be in flight
        __syncthreads();

        if (kt + 2 < nkt)
            loadKV((kt + 2) % 3, kt + 2);
        CP_COMMIT();

        const __half* Ks = hsm + OFF_K + stg * KSTG;
        const __half* Vs = hsm + OFF_V + stg * KSTG;
        const int ktBase = kt * 64;

        // S = Q K^T (raw)
        float sc[8][4];
#pragma unroll
        for (int ni = 0; ni < 8; ++ni)
#pragma unroll
            for (int r = 0; r < 4; ++r) sc[ni][r] = 0.0f;

#pragma unroll
        for (int s = 0; s < 4; ++s) {
            const int ko = s * 16 + 2 * t4;
#pragma unroll
            for (int ni = 0; ni < 8; ++ni) {
                uint32_t bb[2];
                bb[0] = U32(&Ks[(ni * 8 + g) * AQP + ko]);
                bb[1] = U32(&Ks[(ni * 8 + g) * AQP + ko + 8]);
                mma_f16(sc[ni], qf[s], bb);
            }
        }

        // scale (exact fp32) then causal mask
#pragma unroll
        for (int ni = 0; ni < 8; ++ni)
#pragma unroll
            for (int r = 0; r < 4; ++r) sc[ni][r] *= ASCALE;

        if (ktBase + 63 > qBase + wrow) {
            const int r0 = qBase + wrow + g;
            const int r1 = r0 + 8;
#pragma unroll
            for (int ni = 0; ni < 8; ++ni) {
                int c0 = ktBase + ni * 8 + 2 * t4;
                int c1 = c0 + 1;
                if (c0 > r0) sc[ni][0] = -1e30f;
                if (c1 > r0) sc[ni][1] = -1e30f;
                if (c0 > r1) sc[ni][2] = -1e30f;
                if (c1 > r1) sc[ni][3] = -1e30f;
            }
        }

        // Online softmax (base-2), quad-reduce
#pragma unroll
        for (int hrow = 0; hrow < 2; ++hrow) {
            const int i0 = hrow * 2, i1 = hrow * 2 + 1;
            float tm = -INFINITY;
#pragma unroll
            for (int ni = 0; ni < 8; ++ni)
                tm = fmaxf(tm, fmaxf(sc[ni][i0], sc[ni][i1]));
            tm = fmaxf(tm, __shfl_xor_sync(0xffffffffu, tm, 1, 4));
            tm = fmaxf(tm, __shfl_xor_sync(0xffffffffu, tm, 2, 4));
            float m_new = fmaxf(m_i[hrow], tm);
            float alpha = exp2f(m_i[hrow] - m_new);
            float rs = 0.0f;
#pragma unroll
            for (int ni = 0; ni < 8; ++ni) {
                sc[ni][i0] = exp2f(sc[ni][i0] - m_new);
                sc[ni][i1] = exp2f(sc[ni][i1] - m_new);
                rs += sc[ni][i0] + sc[ni][i1];
            }
            rs += __shfl_xor_sync(0xffffffffu, rs, 1, 4);
            rs += __shfl_xor_sync(0xffffffffu, rs, 2, 4);
            l_i[hrow] = l_i[hrow] * alpha + rs;
            m_i[hrow] = m_new;
#pragma unroll
            for (int ni = 0; ni < 8; ++ni) {
                O[ni][i0] *= alpha;
                O[ni][i1] *= alpha;
            }
        }

        // P -> QP smem as fp16 (half2 stores, warp-private rows)
#pragma unroll
        for (int ni = 0; ni < 8; ++ni) {
            __half2 p0 = __floats2half2_rn(sc[ni][0], sc[ni][1]);
            __half2 p1 = __floats2half2_rn(sc[ni][2], sc[ni][3]);
            *(__half2*)&QP[(wrow + g    ) * AQP + ni * 8 + 2 * t4] = p0;
            *(__half2*)&QP[(wrow + g + 8) * AQP + ni * 8 + 2 * t4] = p1;
        }
        __syncwarp();

        // O += P @ V  (B from V^T [d][key] -> contiguous key pairs)
#pragma unroll
        for (int s = 0; s < 4; ++s) {
            const int ko = s * 16 + 2 * t4;
            uint32_t a[4];
            a[0] = U32(&QP[(wrow + g    ) * AQP + ko]);
            a[1] = U32(&QP[(wrow + g + 8) * AQP + ko]);
            a[2] = U32(&QP[(wrow + g    ) * AQP + ko + 8]);
            a[3] = U32(&QP[(wrow + g + 8) * AQP + ko + 8]);
#pragma unroll
            for (int ni = 0; ni < 8; ++ni) {
                uint32_t bb[2];
                bb[0] = U32(&Vs[(ni * 8 + g) * AQP + ko]);
                bb[1] = U32(&Vs[(ni * 8 + g) * AQP + ko + 8]);
                mma_f16(O[ni], a, bb);
            }
        }
    }

    // Epilogue: normalize, fp16, plain layout
    __half* ob = att + (size_t)(b * SEQ + qBase + wrow) * DIM + h * HD;
    const float inv0 = 1.0f / l_i[0];
    const float inv1 = 1.0f / l_i[1];
#pragma unroll
    for (int ni = 0; ni < 8; ++ni) {
        int col = ni * 8 + 2 * t4;
        __half2 o0 = __floats2half2_rn(O[ni][0] * inv0, O[ni][1] * inv0);
        __half2 o1 = __floats2half2_rn(O[ni][2] * inv1, O[ni][3] * inv1);
        *(__half2*)(ob + (size_t)(g    ) * DIM + col) = o0;
        *(__half2*)(ob + (size_t)(g + 8) * DIM + col) = o1;
    }
}

// ---------------------------------------------------------------------------
extern "C" void kernel_launch(void* const* d_in, const int* in_sizes, int n_in,
                              void* d_out, int out_size)
{
    const float* x     = (const float*)d_in[0];
    const float* w_qkv = (const float*)d_in[1];
    const float* b_qkv = (const float*)d_in[2];
    const float* w_out = (const float*)d_in[3];
    const float* b_out = (const float*)d_in[4];
    float* out = (float*)d_out;

    __half *x16, *w1h, *w2h, *qkv16, *vT16, *att16;
    cudaGetSymbolAddress((void**)&x16,   g_x16);
    cudaGetSymbolAddress((void**)&w1h,   g_w1h);
    cudaGetSymbolAddress((void**)&w2h,   g_w2h);
    cudaGetSymbolAddress((void**)&qkv16, g_qkv);
    cudaGetSymbolAddress((void**)&vT16,  g_vT);
    cudaGetSymbolAddress((void**)&att16, g_att);

    // 0) Convert inputs to fp16 (x plain; weights transposed to [N][K])
    round_h<<<512, 256>>>(x, x16, (int)((size_t)M_TOT * DIM / 4));
    transpose_round_h<<<dim3(D3 / 32, DIM / 32), dim3(32, 8)>>>(w_qkv, w1h, DIM, D3);
    transpose_round_h<<<dim3(DIM / 32, DIM / 32), dim3(32, 8)>>>(w_out, w2h, DIM, DIM);

    cudaFuncSetAttribute(gemm_h<1>, cudaFuncAttributeMaxDynamicSharedMemorySize, GSMEM);
    cudaFuncSetAttribute(gemm_h<0>, cudaFuncAttributeMaxDynamicSharedMemorySize, GSMEM);

    // 1) QKV projection (fp16 out)
    gemm_h<1><<<dim3(D3 / 128, M_TOT / 128), 256, GSMEM>>>(
        x16, w1h, b_qkv, qkv16, M_TOT, D3, DIM);

    // 1b) V -> V^T [b,h,d,key]
    v_to_vT<<<dim3(SEQ / 64, NH, B_SZ), 256>>>(qkv16, vT16);

    // 2) Causal flash attention (fp16 MMA, 3-stage pipeline)
    cudaFuncSetAttribute(attn_fwd_h, cudaFuncAttributeMaxDynamicSharedMemorySize, ATT_SMEM);
    attn_fwd_h<<<dim3(SEQ / 128, NH, B_SZ), 256, ATT_SMEM>>>(qkv16, vT16, att16);

    // 3) Output projection (fp32 out)
    gemm_h<0><<<dim3(DIM / 128, M_TOT / 128), 256, GSMEM>>>(
        att16, w2h, b_out, out, M_TOT, DIM, DIM);
}